// round 11
// baseline (speedup 1.0000x reference)
#include <cuda_runtime.h>
#include <cuda_fp16.h>
#include <cstdint>

static constexpr int B_=4, T_=1024, C_=768, H_=12;
static constexpr long BT=4096, YN=BT*C_, AN=48L*1024*1024;

__device__ __align__(1024) half g_xh[YN], g_xl[YN];
__device__ __align__(1024) half g_wq[2304L*768];
__device__ __align__(1024) half g_wp[768L*768];
__device__ __align__(1024) half g_qh[YN], g_ql[YN];
__device__ __align__(1024) half g_kk[YN];
__device__ __align__(1024) half g_vv[YN], g_vt[YN];
__device__ __align__(1024) float g_logits[AN];
__device__ __align__(1024) half g_ah[AN], g_al[AN];   // normalized attn hi/lo
__device__ __align__(1024) half g_yh[YN], g_yl[YN];

// ---------------- helpers ----------------
__device__ __forceinline__ uint32_t smem_u32(const void* p){
    uint32_t a; asm("{ .reg .u64 t; cvta.to.shared.u64 t, %1; cvt.u32.u64 %0, t; }":"=r"(a):"l"(p)); return a;
}
__device__ __forceinline__ void mma16816(float* c, const uint32_t* a, const uint32_t* b){
    asm volatile("mma.sync.aligned.m16n8k16.row.col.f32.f16.f16.f32 "
        "{%0,%1,%2,%3}, {%4,%5,%6,%7}, {%8,%9}, {%0,%1,%2,%3};"
        : "+f"(c[0]),"+f"(c[1]),"+f"(c[2]),"+f"(c[3])
        : "r"(a[0]),"r"(a[1]),"r"(a[2]),"r"(a[3]),"r"(b[0]),"r"(b[1]));
}
__device__ __forceinline__ void ldsm4(uint32_t* r, uint32_t addr){
    asm volatile("ldmatrix.sync.aligned.m8n8.x4.shared.b16 {%0,%1,%2,%3}, [%4];"
        : "=r"(r[0]),"=r"(r[1]),"=r"(r[2]),"=r"(r[3]) : "r"(addr));
}
__device__ __forceinline__ void ldsm2(uint32_t* r, uint32_t addr){
    asm volatile("ldmatrix.sync.aligned.m8n8.x2.shared.b16 {%0,%1}, [%2];"
        : "=r"(r[0]),"=r"(r[1]) : "r"(addr));
}
__device__ __forceinline__ void cpasync16(uint32_t dst, const void* src){
    asm volatile("cp.async.cg.shared.global [%0], [%1], 16;" :: "r"(dst), "l"(src));
}
__device__ __forceinline__ void cpcommit(){ asm volatile("cp.async.commit_group;" ::: "memory"); }
template<int N> __device__ __forceinline__ void cpwait(){ asm volatile("cp.async.wait_group %0;" :: "n"(N) : "memory"); }
__device__ __forceinline__ uint32_t pack_h(float a, float b){
    half2 t = __floats2half2_rn(a,b);
    return *reinterpret_cast<uint32_t*>(&t);
}
__device__ __forceinline__ void split2(float v, float& h, float& l){
    half hb = __float2half_rn(v); h = __half2float(hb); l = v - h;
}

// ---------------------------------------------------------------------------
// TN-form fp16 tensor-core GEMM, one-sided hi/lo split (2 products), fused
// tile loads, cp.async double-buffered, direct fragment epilogues.
// A:[M,K] split (Ah,Al), B:[N,K] single; C = (Ah+Al)*B^T fp32.
// MODE 0:qkv  1:logits(fp32)  2:proj  3:AV
// __launch_bounds__(256,3): cap regs at 85 to get 3 CTAs/SM.
// ---------------------------------------------------------------------------
template<int MODE>
__global__ __launch_bounds__(256, 3)
void gemm_tc(const half* __restrict__ Ah, const half* __restrict__ Al,
             const half* __restrict__ Bs,
             const float* __restrict__ bias1, const float* __restrict__ biasM,
             const float* __restrict__ maskM, float* __restrict__ outF,
             half* __restrict__ o1h, half* __restrict__ o1l,
             half* __restrict__ o2h, half* __restrict__ o3h)
{
    constexpr int TN  = (MODE==3)?64:128;
    constexpr int NF  = TN/32;
    constexpr int KT  = (MODE==1)?64:((MODE==3)?1024:768);
    constexpr long LDA = (MODE==3)?1024:768;
    constexpr long LDB = (MODE==3)?1024:768;
    constexpr int NKT = KT/32;
    constexpr uint32_t TSA  = 10240u;          // 128x32 fp16 tile, 80B pitch
    constexpr uint32_t TSB  = TN*80u;
    constexpr uint32_t BUFB = 2u*TSA + TSB;

    extern __shared__ half smem[];
    const uint32_t sb0 = smem_u32(smem);

    const int tid = threadIdx.x, wid = tid>>5, lane = tid&31;
    const int wr = wid>>2, wc = wid&3;
    const int m_w = wr*64, n_w = wc*(TN/4);
    const int m0 = blockIdx.y*128, n0 = blockIdx.x*TN;
    const int bz = blockIdx.z, bb = bz/H_, hh = bz - bb*H_;

    long aOff, bOff;
    if (MODE==1){ aOff = ((long)bb*1024 + m0)*768 + hh*64; bOff = ((long)bb*1024 + n0)*768 + hh*64; }
    else if (MODE==3){ aOff = (long)bz*1048576 + (long)m0*1024; bOff = (long)bz*65536; }
    else { aOff = (long)m0*LDA; bOff = (long)n0*LDB; }
    const half *pAh=Ah+aOff, *pAl=Al+aOff, *pB=Bs+bOff;

    float acc[4][NF][4];
    #pragma unroll
    for(int i=0;i<4;i++)
        #pragma unroll
        for(int j=0;j<NF;j++)
            #pragma unroll
            for(int k=0;k<4;k++) acc[i][j][k]=0.f;

    const uint32_t aAddrB = sb0 + (uint32_t)(m_w + (lane&15))*80u + (uint32_t)(lane>>4)*16u;
    const uint32_t bAddrB = sb0 + (uint32_t)(n_w + (lane&7))*80u + (uint32_t)((lane>>3)&1)*16u;

    auto issue = [&](int kt, int buf){
        const long k0 = (long)kt*32;
        const uint32_t base = sb0 + (uint32_t)buf*BUFB;
        #pragma unroll
        for(int it=0; it<4; ++it){                 // A hi+lo: 1024 x 16B
            const int i = tid + it*256;
            const int t = i>>9, j = i&511, r = j>>2, c = j&3;
            const half* src = (t? pAl : pAh) + (long)r*LDA + k0 + c*8;
            cpasync16(base + (uint32_t)t*TSA + (uint32_t)(r*80 + c*16), src);
        }
        #pragma unroll
        for(int it=0; it<TN/64; ++it){             // B single: TN*4 x 16B
            const int i = tid + it*256;
            const int r = i>>2, c = i&3;
            const half* src = pB + (long)r*LDB + k0 + c*8;
            cpasync16(base + 2u*TSA + (uint32_t)(r*80 + c*16), src);
        }
        cpcommit();
    };

    issue(0, 0);
    for(int kt=0; kt<NKT; ++kt){
        const int cb = kt&1;
        if (kt+1 < NKT){ issue(kt+1, cb^1); cpwait<1>(); }
        else           { cpwait<0>(); }
        __syncthreads();

        const uint32_t aH = aAddrB + (uint32_t)cb*BUFB;
        const uint32_t aL = aH + TSA;
        const uint32_t bB = bAddrB + (uint32_t)cb*BUFB + 2u*TSA;
        #pragma unroll
        for(int kf=0; kf<2; ++kf){
            uint32_t a4[4][4], b2[NF][2];
            #pragma unroll
            for(int mf=0; mf<4; ++mf) ldsm4(a4[mf], aH + (uint32_t)mf*1280u + (uint32_t)kf*32u);
            #pragma unroll
            for(int nf=0; nf<NF; ++nf) ldsm2(b2[nf], bB + (uint32_t)nf*640u + (uint32_t)kf*32u);
            #pragma unroll
            for(int mf=0; mf<4; ++mf)
                #pragma unroll
                for(int nf=0; nf<NF; ++nf) mma16816(acc[mf][nf], a4[mf], b2[nf]);   // Ah*B
            #pragma unroll
            for(int mf=0; mf<4; ++mf) ldsm4(a4[mf], aL + (uint32_t)mf*1280u + (uint32_t)kf*32u);
            #pragma unroll
            for(int mf=0; mf<4; ++mf)
                #pragma unroll
                for(int nf=0; nf<NF; ++nf) mma16816(acc[mf][nf], a4[mf], b2[nf]);   // Al*B
        }
        __syncthreads();
    }

    // ---------------- direct fragment epilogue ----------------
    const int qd = lane>>2, rr = lane&3;
    #pragma unroll
    for(int mf=0;mf<4;++mf){
        #pragma unroll
        for(int nf=0;nf<NF;++nf){
            const float* c = acc[mf][nf];
            const int mrow0 = m_w + mf*16 + qd;
            const int ncol  = n_w + nf*8 + rr*2;
            #pragma unroll
            for(int h2=0;h2<2;++h2){
                const int mloc = mrow0 + h2*8;
                float v0 = c[h2*2+0], v1 = c[h2*2+1];
                if (MODE==1){
                    const long rowg  = (long)bz*1048576 + (long)(m0+mloc)*1024 + n0 + ncol;
                    const long maskg = (long)bb*1048576 + (long)(m0+mloc)*1024 + n0 + ncol;
                    float2 bm = *reinterpret_cast<const float2*>(biasM + rowg);
                    float2 mk = *reinterpret_cast<const float2*>(maskM + maskg);
                    float2 o; o.x = v0 + bm.x + mk.x; o.y = v1 + bm.y + mk.y;
                    *reinterpret_cast<float2*>(outF + rowg) = o;
                } else if (MODE==2){
                    const int ng = n0 + ncol;
                    float2 o; o.x = v0 + bias1[ng]; o.y = v1 + bias1[ng+1];
                    *reinterpret_cast<float2*>(outF + (long)(m0+mloc)*768 + ng) = o;
                } else if (MODE==0){
                    const int ng = n0 + ncol;
                    v0 += bias1[ng]; v1 += bias1[ng+1];
                    if (n0 < 768){            // q: scaled, split hi/lo
                        v0 *= 0.125f; v1 *= 0.125f;
                        float h0,l0,h1,l1; split2(v0,h0,l0); split2(v1,h1,l1);
                        const long ob = (long)(m0+mloc)*768 + ng;
                        *reinterpret_cast<uint32_t*>(o1h+ob) = pack_h(h0,h1);
                        *reinterpret_cast<uint32_t*>(o1l+ob) = pack_h(l0,l1);
                    } else if (n0 < 1536){    // k: single fp16
                        const long ob = (long)(m0+mloc)*768 + ng - 768;
                        *reinterpret_cast<uint32_t*>(o2h+ob) = pack_h(v0,v1);
                    } else {                  // v: single fp16
                        const long ob = (long)(m0+mloc)*768 + ng - 1536;
                        *reinterpret_cast<uint32_t*>(o3h+ob) = pack_h(v0,v1);
                    }
                } else { // MODE 3: y split
                    float h0,l0,h1,l1; split2(v0,h0,l0); split2(v1,h1,l1);
                    const long ob = ((long)bb*1024 + m0 + mloc)*768 + hh*64 + ncol;
                    *reinterpret_cast<uint32_t*>(o1h+ob) = pack_h(h0,h1);
                    *reinterpret_cast<uint32_t*>(o1l+ob) = pack_h(l0,l1);
                }
            }
        }
    }
}

// softmax over 1024-wide rows: fp32 logits -> fp32 attn + fp16 hi/lo attn
__global__ __launch_bounds__(256) void softmax_kernel(const float* __restrict__ in, float* __restrict__ out,
                                                      half* __restrict__ oh, half* __restrict__ ol){
    const long row = blockIdx.x;
    const int tid = threadIdx.x;
    __shared__ float sred[8];
    float4 v = *reinterpret_cast<const float4*>(in + row*1024 + tid*4);
    float m = fmaxf(fmaxf(v.x,v.y), fmaxf(v.z,v.w));
    #pragma unroll
    for(int o=16;o;o>>=1) m = fmaxf(m, __shfl_xor_sync(0xffffffffu,m,o));
    if((tid&31)==0) sred[tid>>5]=m;
    __syncthreads();
    float gm = sred[0];
    #pragma unroll
    for(int i=1;i<8;i++) gm = fmaxf(gm, sred[i]);
    __syncthreads();
    v.x=__expf(v.x-gm); v.y=__expf(v.y-gm); v.z=__expf(v.z-gm); v.w=__expf(v.w-gm);
    float s = v.x+v.y+v.z+v.w;
    #pragma unroll
    for(int o=16;o;o>>=1) s += __shfl_xor_sync(0xffffffffu,s,o);
    if((tid&31)==0) sred[tid>>5]=s;
    __syncthreads();
    float gs = sred[0];
    #pragma unroll
    for(int i=1;i<8;i++) gs += sred[i];
    const float inv = 1.0f/gs;
    v.x*=inv; v.y*=inv; v.z*=inv; v.w*=inv;
    *reinterpret_cast<float4*>(out + row*1024 + tid*4) = v;
    float h0,l0,h1,l1,h2,l2,h3,l3;
    split2(v.x,h0,l0); split2(v.y,h1,l1); split2(v.z,h2,l2); split2(v.w,h3,l3);
    *reinterpret_cast<uint2*>(oh + row*1024 + tid*4) = make_uint2(pack_h(h0,h1), pack_h(h2,h3));
    *reinterpret_cast<uint2*>(ol + row*1024 + tid*4) = make_uint2(pack_h(l0,l1), pack_h(l2,l3));
}

// fp32 -> fp16 hi/lo elementwise split
__global__ __launch_bounds__(256) void splitk(const float4* __restrict__ in,
                                              half* __restrict__ oh, half* __restrict__ ol, long n4){
    long i = (long)blockIdx.x*256 + threadIdx.x;
    if (i >= n4) return;
    float4 v = in[i];
    float h0,l0,h1,l1,h2,l2,h3,l3;
    split2(v.x,h0,l0); split2(v.y,h1,l1); split2(v.z,h2,l2); split2(v.w,h3,l3);
    *reinterpret_cast<uint2*>(oh + i*4) = make_uint2(pack_h(h0,h1), pack_h(h2,h3));
    *reinterpret_cast<uint2*>(ol + i*4) = make_uint2(pack_h(l0,l1), pack_h(l2,l3));
}

// W [K,N] fp32 -> Wt [N,K] single fp16
__global__ __launch_bounds__(256) void wtsplit(const float* __restrict__ W,
                                               half* __restrict__ oh, int K, int N){
    __shared__ float tf[32][33];
    const int n0 = blockIdx.x*32, k0 = blockIdx.y*32;
    const int tx = threadIdx.x&31, ty = threadIdx.x>>5;
    #pragma unroll
    for(int i=0;i<4;i++) tf[ty+8*i][tx] = W[(long)(k0+ty+8*i)*N + n0+tx];
    __syncthreads();
    #pragma unroll
    for(int i=0;i<4;i++){
        long o = (long)(n0+ty+8*i)*K + k0+tx;
        oh[o] = __float2half_rn(tf[tx][ty+8*i]);
    }
}

// v [B,T,H*64] -> vt [B*H, 64, 1024] single fp16
__global__ __launch_bounds__(256) void vtrans(const half* __restrict__ ih, half* __restrict__ oh){
    __shared__ half th[32][34];
    const int t0 = blockIdx.x*32, d0 = blockIdx.y*32, bz = blockIdx.z;
    const int bb = bz/H_, hh = bz - bb*H_;
    const int tx = threadIdx.x&31, ty = threadIdx.x>>5;
    const long ib = ((long)bb*1024 + t0)*768 + hh*64 + d0;
    #pragma unroll
    for(int i=0;i<4;i++) th[ty+8*i][tx] = ih[ib + (long)(ty+8*i)*768 + tx];
    __syncthreads();
    const long ob = ((long)bz*64 + d0)*1024 + t0;
    #pragma unroll
    for(int i=0;i<4;i++) oh[ob + (long)(ty+8*i)*1024 + tx] = th[tx][ty+8*i];
}

extern "C" void kernel_launch(void* const* d_in, const int* in_sizes, int n_in,
                              void* d_out, int out_size)
{
    const float* x     = (const float*)d_in[0];
    const float* mask  = (const float*)d_in[1];
    const float* bias  = (const float*)d_in[2];
    const float* Wqkv  = (const float*)d_in[3];
    const float* bqkv  = (const float*)d_in[4];
    const float* Wproj = (const float*)d_in[5];
    const float* bproj = (const float*)d_in[6];
    float* out = (float*)d_out;

    half *xh,*xl,*wq,*wp,*qh,*ql,*kk,*vv,*vt,*ah,*al,*yh,*yl;
    float *logits;
    cudaGetSymbolAddress((void**)&xh,g_xh);   cudaGetSymbolAddress((void**)&xl,g_xl);
    cudaGetSymbolAddress((void**)&wq,g_wq);   cudaGetSymbolAddress((void**)&wp,g_wp);
    cudaGetSymbolAddress((void**)&qh,g_qh);   cudaGetSymbolAddress((void**)&ql,g_ql);
    cudaGetSymbolAddress((void**)&kk,g_kk);   cudaGetSymbolAddress((void**)&vv,g_vv);
    cudaGetSymbolAddress((void**)&vt,g_vt);
    cudaGetSymbolAddress((void**)&ah,g_ah);   cudaGetSymbolAddress((void**)&al,g_al);
    cudaGetSymbolAddress((void**)&yh,g_yh);   cudaGetSymbolAddress((void**)&yl,g_yl);
    cudaGetSymbolAddress((void**)&logits,g_logits);

    float* attn = ((long)out_size >= YN + AN) ? (out + YN) : logits;

    const int smemBig = 61440;   // 2*(2*10240 + 10240)
    const int smemAV  = 51200;   // 2*(2*10240 + 5120)
    cudaFuncSetAttribute(gemm_tc<0>, cudaFuncAttributeMaxDynamicSharedMemorySize, smemBig);
    cudaFuncSetAttribute(gemm_tc<1>, cudaFuncAttributeMaxDynamicSharedMemorySize, smemBig);
    cudaFuncSetAttribute(gemm_tc<2>, cudaFuncAttributeMaxDynamicSharedMemorySize, smemBig);
    cudaFuncSetAttribute(gemm_tc<3>, cudaFuncAttributeMaxDynamicSharedMemorySize, smemAV);

    // 1) split x into fp16 hi/lo
    splitk<<<(YN/4+255)/256, 256>>>((const float4*)x, xh, xl, YN/4);
    // 2) transpose weights to [N,K] single fp16
    wtsplit<<<dim3(2304/32, 768/32), 256>>>(Wqkv, wq, 768, 2304);
    wtsplit<<<dim3(768/32, 768/32),  256>>>(Wproj, wp, 768, 768);
    // 3) qkv GEMM -> q(scaled, split) / k / v
    gemm_tc<0><<<dim3(18,32,1), 256, smemBig>>>(xh, xl, wq, bqkv, nullptr, nullptr, nullptr,
                                                qh, ql, kk, vv);
    // 4) transpose v -> [B*H,64,1024]
    vtrans<<<dim3(32,2,48), 256>>>(vv, vt);
    // 5) logits fp32 = q k^T + bias + mask
    gemm_tc<1><<<dim3(8,8,48), 256, smemBig>>>(qh, ql, kk, nullptr, bias, mask, logits,
                                               nullptr, nullptr, nullptr, nullptr);
    // 6) softmax -> attn fp32 + attn hi/lo fp16
    softmax_kernel<<<48*1024, 256>>>(logits, attn, ah, al);
    // 7) y = attn @ v^T (split output)
    gemm_tc<3><<<dim3(1,8,48), 256, smemAV>>>(ah, al, vt, nullptr, nullptr, nullptr, nullptr,
                                              yh, yl, nullptr, nullptr);
    // 8) out = y @ Wproj + bproj
    gemm_tc<2><<<dim3(6,32,1), 256, smemBig>>>(yh, yl, wp, bproj, nullptr, nullptr, out,
                                               nullptr, nullptr, nullptr, nullptr);
}

// round 12
// speedup vs baseline: 1.3079x; 1.3079x over previous
#include <cuda_runtime.h>
#include <cuda_fp16.h>
#include <cstdint>

static constexpr int B_=4, T_=1024, C_=768, H_=12;
static constexpr long BT=4096, YN=BT*C_, AN=48L*1024*1024;

__device__ __align__(1024) half g_xh[YN], g_xl[YN];
__device__ __align__(1024) half g_wq[2304L*768];
__device__ __align__(1024) half g_wp[768L*768];
__device__ __align__(1024) half g_qh[YN], g_ql[YN];
__device__ __align__(1024) half g_kk[YN];
__device__ __align__(1024) half g_vv[YN], g_vt[YN];
__device__ __align__(1024) float g_logits[AN];
__device__ __align__(1024) half g_ah[AN], g_al[AN];   // normalized attn hi/lo
__device__ __align__(1024) half g_yh[YN], g_yl[YN];

// ---------------- helpers ----------------
__device__ __forceinline__ uint32_t smem_u32(const void* p){
    uint32_t a; asm("{ .reg .u64 t; cvta.to.shared.u64 t, %1; cvt.u32.u64 %0, t; }":"=r"(a):"l"(p)); return a;
}
__device__ __forceinline__ void mma16816(float* c, const uint32_t* a, const uint32_t* b){
    asm volatile("mma.sync.aligned.m16n8k16.row.col.f32.f16.f16.f32 "
        "{%0,%1,%2,%3}, {%4,%5,%6,%7}, {%8,%9}, {%0,%1,%2,%3};"
        : "+f"(c[0]),"+f"(c[1]),"+f"(c[2]),"+f"(c[3])
        : "r"(a[0]),"r"(a[1]),"r"(a[2]),"r"(a[3]),"r"(b[0]),"r"(b[1]));
}
__device__ __forceinline__ void ldsm4(uint32_t* r, uint32_t addr){
    asm volatile("ldmatrix.sync.aligned.m8n8.x4.shared.b16 {%0,%1,%2,%3}, [%4];"
        : "=r"(r[0]),"=r"(r[1]),"=r"(r[2]),"=r"(r[3]) : "r"(addr));
}
__device__ __forceinline__ void ldsm2(uint32_t* r, uint32_t addr){
    asm volatile("ldmatrix.sync.aligned.m8n8.x2.shared.b16 {%0,%1}, [%2];"
        : "=r"(r[0]),"=r"(r[1]) : "r"(addr));
}
__device__ __forceinline__ void cpasync16(uint32_t dst, const void* src){
    asm volatile("cp.async.cg.shared.global [%0], [%1], 16;" :: "r"(dst), "l"(src));
}
__device__ __forceinline__ void cpcommit(){ asm volatile("cp.async.commit_group;" ::: "memory"); }
template<int N> __device__ __forceinline__ void cpwait(){ asm volatile("cp.async.wait_group %0;" :: "n"(N) : "memory"); }
__device__ __forceinline__ uint32_t pack_h(float a, float b){
    half2 t = __floats2half2_rn(a,b);
    return *reinterpret_cast<uint32_t*>(&t);
}
__device__ __forceinline__ void split2(float v, float& h, float& l){
    half hb = __float2half_rn(v); h = __half2float(hb); l = v - h;
}

// ---------------------------------------------------------------------------
// TN-form fp16 tensor-core GEMM, one-sided hi/lo split (2 products), fused
// tile loads, 3-stage cp.async pipeline, direct fragment epilogues.
// A:[M,K] split (Ah,Al), B:[N,K] single; C = (Ah+Al)*B^T fp32.
// MODE 0:qkv  1:logits(fp32)  2:proj  3:AV
// ---------------------------------------------------------------------------
template<int MODE>
__global__ __launch_bounds__(256)
void gemm_tc(const half* __restrict__ Ah, const half* __restrict__ Al,
             const half* __restrict__ Bs,
             const float* __restrict__ bias1, const float* __restrict__ biasM,
             const float* __restrict__ maskM, float* __restrict__ outF,
             half* __restrict__ o1h, half* __restrict__ o1l,
             half* __restrict__ o2h, half* __restrict__ o3h)
{
    constexpr int TN  = (MODE==3)?64:128;
    constexpr int NF  = TN/32;
    constexpr int KT  = (MODE==1)?64:((MODE==3)?1024:768);
    constexpr long LDA = (MODE==3)?1024:768;
    constexpr long LDB = (MODE==3)?1024:768;
    constexpr int NKT = KT/32;
    constexpr uint32_t TSA  = 10240u;          // 128x32 fp16 tile, 80B pitch
    constexpr uint32_t TSB  = TN*80u;
    constexpr uint32_t BUFB = 2u*TSA + TSB;

    extern __shared__ half smem[];
    const uint32_t sb0 = smem_u32(smem);

    const int tid = threadIdx.x, wid = tid>>5, lane = tid&31;
    const int wr = wid>>2, wc = wid&3;
    const int m_w = wr*64, n_w = wc*(TN/4);
    const int m0 = blockIdx.y*128, n0 = blockIdx.x*TN;
    const int bz = blockIdx.z, bb = bz/H_, hh = bz - bb*H_;

    long aOff, bOff;
    if (MODE==1){ aOff = ((long)bb*1024 + m0)*768 + hh*64; bOff = ((long)bb*1024 + n0)*768 + hh*64; }
    else if (MODE==3){ aOff = (long)bz*1048576 + (long)m0*1024; bOff = (long)bz*65536; }
    else { aOff = (long)m0*LDA; bOff = (long)n0*LDB; }
    const half *pAh=Ah+aOff, *pAl=Al+aOff, *pB=Bs+bOff;

    float acc[4][NF][4];
    #pragma unroll
    for(int i=0;i<4;i++)
        #pragma unroll
        for(int j=0;j<NF;j++)
            #pragma unroll
            for(int k=0;k<4;k++) acc[i][j][k]=0.f;

    const uint32_t aAddrB = sb0 + (uint32_t)(m_w + (lane&15))*80u + (uint32_t)(lane>>4)*16u;
    const uint32_t bAddrB = sb0 + (uint32_t)(n_w + (lane&7))*80u + (uint32_t)((lane>>3)&1)*16u;

    auto issue = [&](int kt, int buf){
        const long k0 = (long)kt*32;
        const uint32_t base = sb0 + (uint32_t)buf*BUFB;
        #pragma unroll
        for(int it=0; it<4; ++it){                 // A hi+lo: 1024 x 16B
            const int i = tid + it*256;
            const int t = i>>9, j = i&511, r = j>>2, c = j&3;
            const half* src = (t? pAl : pAh) + (long)r*LDA + k0 + c*8;
            cpasync16(base + (uint32_t)t*TSA + (uint32_t)(r*80 + c*16), src);
        }
        #pragma unroll
        for(int it=0; it<TN/64; ++it){             // B single: TN*4 x 16B
            const int i = tid + it*256;
            const int r = i>>2, c = i&3;
            const half* src = pB + (long)r*LDB + k0 + c*8;
            cpasync16(base + 2u*TSA + (uint32_t)(r*80 + c*16), src);
        }
        cpcommit();
    };

    // 3-stage prologue
    issue(0, 0);
    if (NKT > 1) issue(1, 1);

    int cb = 0;
    for(int kt=0; kt<NKT; ++kt){
        if (kt+2 < NKT){ issue(kt+2, (kt+2)%3); cpwait<2>(); }
        else if (kt+1 < NKT){ cpwait<1>(); }
        else { cpwait<0>(); }
        __syncthreads();

        const uint32_t aH = aAddrB + (uint32_t)cb*BUFB;
        const uint32_t aL = aH + TSA;
        const uint32_t bB = bAddrB + (uint32_t)cb*BUFB + 2u*TSA;
        #pragma unroll
        for(int kf=0; kf<2; ++kf){
            uint32_t a4[4][4], b2[NF][2];
            #pragma unroll
            for(int mf=0; mf<4; ++mf) ldsm4(a4[mf], aH + (uint32_t)mf*1280u + (uint32_t)kf*32u);
            #pragma unroll
            for(int nf=0; nf<NF; ++nf) ldsm2(b2[nf], bB + (uint32_t)nf*640u + (uint32_t)kf*32u);
            #pragma unroll
            for(int mf=0; mf<4; ++mf)
                #pragma unroll
                for(int nf=0; nf<NF; ++nf) mma16816(acc[mf][nf], a4[mf], b2[nf]);   // Ah*B
            #pragma unroll
            for(int mf=0; mf<4; ++mf) ldsm4(a4[mf], aL + (uint32_t)mf*1280u + (uint32_t)kf*32u);
            #pragma unroll
            for(int mf=0; mf<4; ++mf)
                #pragma unroll
                for(int nf=0; nf<NF; ++nf) mma16816(acc[mf][nf], a4[mf], b2[nf]);   // Al*B
        }
        __syncthreads();
        cb = (cb+1)%3;
    }

    // ---------------- direct fragment epilogue ----------------
    const int qd = lane>>2, rr = lane&3;
    #pragma unroll
    for(int mf=0;mf<4;++mf){
        #pragma unroll
        for(int nf=0;nf<NF;++nf){
            const float* c = acc[mf][nf];
            const int mrow0 = m_w + mf*16 + qd;
            const int ncol  = n_w + nf*8 + rr*2;
            #pragma unroll
            for(int h2=0;h2<2;++h2){
                const int mloc = mrow0 + h2*8;
                float v0 = c[h2*2+0], v1 = c[h2*2+1];
                if (MODE==1){
                    const long rowg  = (long)bz*1048576 + (long)(m0+mloc)*1024 + n0 + ncol;
                    const long maskg = (long)bb*1048576 + (long)(m0+mloc)*1024 + n0 + ncol;
                    float2 bm = *reinterpret_cast<const float2*>(biasM + rowg);
                    float2 mk = *reinterpret_cast<const float2*>(maskM + maskg);
                    float2 o; o.x = v0 + bm.x + mk.x; o.y = v1 + bm.y + mk.y;
                    *reinterpret_cast<float2*>(outF + rowg) = o;
                } else if (MODE==2){
                    const int ng = n0 + ncol;
                    float2 o; o.x = v0 + bias1[ng]; o.y = v1 + bias1[ng+1];
                    *reinterpret_cast<float2*>(outF + (long)(m0+mloc)*768 + ng) = o;
                } else if (MODE==0){
                    const int ng = n0 + ncol;
                    v0 += bias1[ng]; v1 += bias1[ng+1];
                    if (n0 < 768){            // q: scaled, split hi/lo
                        v0 *= 0.125f; v1 *= 0.125f;
                        float h0,l0,h1,l1; split2(v0,h0,l0); split2(v1,h1,l1);
                        const long ob = (long)(m0+mloc)*768 + ng;
                        *reinterpret_cast<uint32_t*>(o1h+ob) = pack_h(h0,h1);
                        *reinterpret_cast<uint32_t*>(o1l+ob) = pack_h(l0,l1);
                    } else if (n0 < 1536){    // k: single fp16
                        const long ob = (long)(m0+mloc)*768 + ng - 768;
                        *reinterpret_cast<uint32_t*>(o2h+ob) = pack_h(v0,v1);
                    } else {                  // v: single fp16
                        const long ob = (long)(m0+mloc)*768 + ng - 1536;
                        *reinterpret_cast<uint32_t*>(o3h+ob) = pack_h(v0,v1);
                    }
                } else { // MODE 3: y split
                    float h0,l0,h1,l1; split2(v0,h0,l0); split2(v1,h1,l1);
                    const long ob = ((long)bb*1024 + m0 + mloc)*768 + hh*64 + ncol;
                    *reinterpret_cast<uint32_t*>(o1h+ob) = pack_h(h0,h1);
                    *reinterpret_cast<uint32_t*>(o1l+ob) = pack_h(l0,l1);
                }
            }
        }
    }
}

// softmax over 1024-wide rows: fp32 logits -> fp32 attn + fp16 hi/lo attn
__global__ __launch_bounds__(256) void softmax_kernel(const float* __restrict__ in, float* __restrict__ out,
                                                      half* __restrict__ oh, half* __restrict__ ol){
    const long row = blockIdx.x;
    const int tid = threadIdx.x;
    __shared__ float sred[8];
    float4 v = *reinterpret_cast<const float4*>(in + row*1024 + tid*4);
    float m = fmaxf(fmaxf(v.x,v.y), fmaxf(v.z,v.w));
    #pragma unroll
    for(int o=16;o;o>>=1) m = fmaxf(m, __shfl_xor_sync(0xffffffffu,m,o));
    if((tid&31)==0) sred[tid>>5]=m;
    __syncthreads();
    float gm = sred[0];
    #pragma unroll
    for(int i=1;i<8;i++) gm = fmaxf(gm, sred[i]);
    __syncthreads();
    v.x=__expf(v.x-gm); v.y=__expf(v.y-gm); v.z=__expf(v.z-gm); v.w=__expf(v.w-gm);
    float s = v.x+v.y+v.z+v.w;
    #pragma unroll
    for(int o=16;o;o>>=1) s += __shfl_xor_sync(0xffffffffu,s,o);
    if((tid&31)==0) sred[tid>>5]=s;
    __syncthreads();
    float gs = sred[0];
    #pragma unroll
    for(int i=1;i<8;i++) gs += sred[i];
    const float inv = 1.0f/gs;
    v.x*=inv; v.y*=inv; v.z*=inv; v.w*=inv;
    *reinterpret_cast<float4*>(out + row*1024 + tid*4) = v;
    float h0,l0,h1,l1,h2,l2,h3,l3;
    split2(v.x,h0,l0); split2(v.y,h1,l1); split2(v.z,h2,l2); split2(v.w,h3,l3);
    *reinterpret_cast<uint2*>(oh + row*1024 + tid*4) = make_uint2(pack_h(h0,h1), pack_h(h2,h3));
    *reinterpret_cast<uint2*>(ol + row*1024 + tid*4) = make_uint2(pack_h(l0,l1), pack_h(l2,l3));
}

// fp32 -> fp16 hi/lo elementwise split
__global__ __launch_bounds__(256) void splitk(const float4* __restrict__ in,
                                              half* __restrict__ oh, half* __restrict__ ol, long n4){
    long i = (long)blockIdx.x*256 + threadIdx.x;
    if (i >= n4) return;
    float4 v = in[i];
    float h0,l0,h1,l1,h2,l2,h3,l3;
    split2(v.x,h0,l0); split2(v.y,h1,l1); split2(v.z,h2,l2); split2(v.w,h3,l3);
    *reinterpret_cast<uint2*>(oh + i*4) = make_uint2(pack_h(h0,h1), pack_h(h2,h3));
    *reinterpret_cast<uint2*>(ol + i*4) = make_uint2(pack_h(l0,l1), pack_h(l2,l3));
}

// W [K,N] fp32 -> Wt [N,K] single fp16
__global__ __launch_bounds__(256) void wtsplit(const float* __restrict__ W,
                                               half* __restrict__ oh, int K, int N){
    __shared__ float tf[32][33];
    const int n0 = blockIdx.x*32, k0 = blockIdx.y*32;
    const int tx = threadIdx.x&31, ty = threadIdx.x>>5;
    #pragma unroll
    for(int i=0;i<4;i++) tf[ty+8*i][tx] = W[(long)(k0+ty+8*i)*N + n0+tx];
    __syncthreads();
    #pragma unroll
    for(int i=0;i<4;i++){
        long o = (long)(n0+ty+8*i)*K + k0+tx;
        oh[o] = __float2half_rn(tf[tx][ty+8*i]);
    }
}

// v [B,T,H*64] -> vt [B*H, 64, 1024] single fp16
__global__ __launch_bounds__(256) void vtrans(const half* __restrict__ ih, half* __restrict__ oh){
    __shared__ half th[32][34];
    const int t0 = blockIdx.x*32, d0 = blockIdx.y*32, bz = blockIdx.z;
    const int bb = bz/H_, hh = bz - bb*H_;
    const int tx = threadIdx.x&31, ty = threadIdx.x>>5;
    const long ib = ((long)bb*1024 + t0)*768 + hh*64 + d0;
    #pragma unroll
    for(int i=0;i<4;i++) th[ty+8*i][tx] = ih[ib + (long)(ty+8*i)*768 + tx];
    __syncthreads();
    const long ob = ((long)bz*64 + d0)*1024 + t0;
    #pragma unroll
    for(int i=0;i<4;i++) oh[ob + (long)(ty+8*i)*1024 + tx] = th[tx][ty+8*i];
}

extern "C" void kernel_launch(void* const* d_in, const int* in_sizes, int n_in,
                              void* d_out, int out_size)
{
    const float* x     = (const float*)d_in[0];
    const float* mask  = (const float*)d_in[1];
    const float* bias  = (const float*)d_in[2];
    const float* Wqkv  = (const float*)d_in[3];
    const float* bqkv  = (const float*)d_in[4];
    const float* Wproj = (const float*)d_in[5];
    const float* bproj = (const float*)d_in[6];
    float* out = (float*)d_out;

    half *xh,*xl,*wq,*wp,*qh,*ql,*kk,*vv,*vt,*ah,*al,*yh,*yl;
    float *logits;
    cudaGetSymbolAddress((void**)&xh,g_xh);   cudaGetSymbolAddress((void**)&xl,g_xl);
    cudaGetSymbolAddress((void**)&wq,g_wq);   cudaGetSymbolAddress((void**)&wp,g_wp);
    cudaGetSymbolAddress((void**)&qh,g_qh);   cudaGetSymbolAddress((void**)&ql,g_ql);
    cudaGetSymbolAddress((void**)&kk,g_kk);   cudaGetSymbolAddress((void**)&vv,g_vv);
    cudaGetSymbolAddress((void**)&vt,g_vt);
    cudaGetSymbolAddress((void**)&ah,g_ah);   cudaGetSymbolAddress((void**)&al,g_al);
    cudaGetSymbolAddress((void**)&yh,g_yh);   cudaGetSymbolAddress((void**)&yl,g_yl);
    cudaGetSymbolAddress((void**)&logits,g_logits);

    float* attn = ((long)out_size >= YN + AN) ? (out + YN) : logits;

    const int smemBig = 92160;   // 3*(2*10240 + 10240)
    const int smemAV  = 76800;   // 3*(2*10240 + 5120)
    cudaFuncSetAttribute(gemm_tc<0>, cudaFuncAttributeMaxDynamicSharedMemorySize, smemBig);
    cudaFuncSetAttribute(gemm_tc<1>, cudaFuncAttributeMaxDynamicSharedMemorySize, smemBig);
    cudaFuncSetAttribute(gemm_tc<2>, cudaFuncAttributeMaxDynamicSharedMemorySize, smemBig);
    cudaFuncSetAttribute(gemm_tc<3>, cudaFuncAttributeMaxDynamicSharedMemorySize, smemAV);

    // 1) split x into fp16 hi/lo
    splitk<<<(YN/4+255)/256, 256>>>((const float4*)x, xh, xl, YN/4);
    // 2) transpose weights to [N,K] single fp16
    wtsplit<<<dim3(2304/32, 768/32), 256>>>(Wqkv, wq, 768, 2304);
    wtsplit<<<dim3(768/32, 768/32),  256>>>(Wproj, wp, 768, 768);
    // 3) qkv GEMM -> q(scaled, split) / k / v
    gemm_tc<0><<<dim3(18,32,1), 256, smemBig>>>(xh, xl, wq, bqkv, nullptr, nullptr, nullptr,
                                                qh, ql, kk, vv);
    // 4) transpose v -> [B*H,64,1024]
    vtrans<<<dim3(32,2,48), 256>>>(vv, vt);
    // 5) logits fp32 = q k^T + bias + mask
    gemm_tc<1><<<dim3(8,8,48), 256, smemBig>>>(qh, ql, kk, nullptr, bias, mask, logits,
                                               nullptr, nullptr, nullptr, nullptr);
    // 6) softmax -> attn fp32 + attn hi/lo fp16
    softmax_kernel<<<48*1024, 256>>>(logits, attn, ah, al);
    // 7) y = attn @ v^T (split output)
    gemm_tc<3><<<dim3(1,8,48), 256, smemAV>>>(ah, al, vt, nullptr, nullptr, nullptr, nullptr,
                                              yh, yl, nullptr, nullptr);
    // 8) out = y @ Wproj + bproj
    gemm_tc<2><<<dim3(6,32,1), 256, smemBig>>>(yh, yl, wp, bproj, nullptr, nullptr, out,
                                               nullptr, nullptr, nullptr, nullptr);
}

// round 13
// speedup vs baseline: 1.4284x; 1.0921x over previous
#include <cuda_runtime.h>
#include <cuda_fp16.h>
#include <cstdint>

static constexpr int B_=4, T_=1024, C_=768, H_=12;
static constexpr long BT=4096, YN=BT*C_, AN=48L*1024*1024;

__device__ __align__(1024) half g_xh[YN], g_xl[YN];
__device__ __align__(1024) half g_wq[2304L*768];
__device__ __align__(1024) half g_wp[768L*768];
__device__ __align__(1024) half g_qh[YN], g_ql[YN];
__device__ __align__(1024) half g_kk[YN];
__device__ __align__(1024) half g_vv[YN], g_vt[YN];
__device__ __align__(1024) float g_logits[AN];
__device__ __align__(1024) half g_ah[AN];             // normalized attn (fp16, hi only)
__device__ __align__(1024) half g_yh[YN], g_yl[YN];

// ---------------- helpers ----------------
__device__ __forceinline__ uint32_t smem_u32(const void* p){
    uint32_t a; asm("{ .reg .u64 t; cvta.to.shared.u64 t, %1; cvt.u32.u64 %0, t; }":"=r"(a):"l"(p)); return a;
}
__device__ __forceinline__ void mma16816(float* c, const uint32_t* a, const uint32_t* b){
    asm volatile("mma.sync.aligned.m16n8k16.row.col.f32.f16.f16.f32 "
        "{%0,%1,%2,%3}, {%4,%5,%6,%7}, {%8,%9}, {%0,%1,%2,%3};"
        : "+f"(c[0]),"+f"(c[1]),"+f"(c[2]),"+f"(c[3])
        : "r"(a[0]),"r"(a[1]),"r"(a[2]),"r"(a[3]),"r"(b[0]),"r"(b[1]));
}
__device__ __forceinline__ void ldsm4(uint32_t* r, uint32_t addr){
    asm volatile("ldmatrix.sync.aligned.m8n8.x4.shared.b16 {%0,%1,%2,%3}, [%4];"
        : "=r"(r[0]),"=r"(r[1]),"=r"(r[2]),"=r"(r[3]) : "r"(addr));
}
__device__ __forceinline__ void ldsm2(uint32_t* r, uint32_t addr){
    asm volatile("ldmatrix.sync.aligned.m8n8.x2.shared.b16 {%0,%1}, [%2];"
        : "=r"(r[0]),"=r"(r[1]) : "r"(addr));
}
__device__ __forceinline__ void cpasync16(uint32_t dst, const void* src){
    asm volatile("cp.async.cg.shared.global [%0], [%1], 16;" :: "r"(dst), "l"(src));
}
__device__ __forceinline__ void cpcommit(){ asm volatile("cp.async.commit_group;" ::: "memory"); }
template<int N> __device__ __forceinline__ void cpwait(){ asm volatile("cp.async.wait_group %0;" :: "n"(N) : "memory"); }
__device__ __forceinline__ uint32_t pack_h(float a, float b){
    half2 t = __floats2half2_rn(a,b);
    return *reinterpret_cast<uint32_t*>(&t);
}
__device__ __forceinline__ void split2(float v, float& h, float& l){
    half hb = __float2half_rn(v); h = __half2float(hb); l = v - h;
}

// ---------------------------------------------------------------------------
// TN-form fp16 tensor-core GEMM. A split hi/lo (2 products) for MODE 0/1/2;
// single-product A for MODE 3 (AV, attn hi only). 3-stage cp.async pipeline.
// A:[M,K], B:[N,K]; C = A*B^T fp32.
// MODE 0:qkv  1:logits(fp32)  2:proj  3:AV
// ---------------------------------------------------------------------------
template<int MODE>
__global__ __launch_bounds__(256)
void gemm_tc(const half* __restrict__ Ah, const half* __restrict__ Al,
             const half* __restrict__ Bs,
             const float* __restrict__ bias1, const float* __restrict__ biasM,
             const float* __restrict__ maskM, float* __restrict__ outF,
             half* __restrict__ o1h, half* __restrict__ o1l,
             half* __restrict__ o2h, half* __restrict__ o3h)
{
    constexpr int TN  = (MODE==3)?64:128;
    constexpr int NF  = TN/32;
    constexpr int NPROD = (MODE==3)?1:2;       // A-side products
    constexpr int KT  = (MODE==1)?64:((MODE==3)?1024:768);
    constexpr long LDA = (MODE==3)?1024:768;
    constexpr long LDB = (MODE==3)?1024:768;
    constexpr int NKT = KT/32;
    constexpr uint32_t TSA  = 10240u;          // 128x32 fp16 tile, 80B pitch
    constexpr uint32_t TSB  = TN*80u;
    constexpr uint32_t BUFB = (uint32_t)NPROD*TSA + TSB;

    extern __shared__ half smem[];
    const uint32_t sb0 = smem_u32(smem);

    const int tid = threadIdx.x, wid = tid>>5, lane = tid&31;
    const int wr = wid>>2, wc = wid&3;
    const int m_w = wr*64, n_w = wc*(TN/4);
    const int m0 = blockIdx.y*128, n0 = blockIdx.x*TN;
    const int bz = blockIdx.z, bb = bz/H_, hh = bz - bb*H_;

    long aOff, bOff;
    if (MODE==1){ aOff = ((long)bb*1024 + m0)*768 + hh*64; bOff = ((long)bb*1024 + n0)*768 + hh*64; }
    else if (MODE==3){ aOff = (long)bz*1048576 + (long)m0*1024; bOff = (long)bz*65536; }
    else { aOff = (long)m0*LDA; bOff = (long)n0*LDB; }
    const half *pAh=Ah+aOff, *pAl=(MODE==3)?nullptr:(Al+aOff), *pB=Bs+bOff;

    float acc[4][NF][4];
    #pragma unroll
    for(int i=0;i<4;i++)
        #pragma unroll
        for(int j=0;j<NF;j++)
            #pragma unroll
            for(int k=0;k<4;k++) acc[i][j][k]=0.f;

    const uint32_t aAddrB = sb0 + (uint32_t)(m_w + (lane&15))*80u + (uint32_t)(lane>>4)*16u;
    const uint32_t bAddrB = sb0 + (uint32_t)(n_w + (lane&7))*80u + (uint32_t)((lane>>3)&1)*16u;

    auto issue = [&](int kt, int buf){
        const long k0 = (long)kt*32;
        const uint32_t base = sb0 + (uint32_t)buf*BUFB;
        #pragma unroll
        for(int it=0; it<2*NPROD; ++it){           // A tiles: 512 chunks per product
            const int i = tid + it*256;
            const int t = i>>9, j = i&511, r = j>>2, c = j&3;
            const half* src = (t? pAl : pAh) + (long)r*LDA + k0 + c*8;
            cpasync16(base + (uint32_t)t*TSA + (uint32_t)(r*80 + c*16), src);
        }
        #pragma unroll
        for(int it=0; it<TN/64; ++it){             // B single: TN*4 x 16B
            const int i = tid + it*256;
            const int r = i>>2, c = i&3;
            const half* src = pB + (long)r*LDB + k0 + c*8;
            cpasync16(base + (uint32_t)NPROD*TSA + (uint32_t)(r*80 + c*16), src);
        }
        cpcommit();
    };

    // 3-stage prologue
    issue(0, 0);
    if (NKT > 1) issue(1, 1);

    int cb = 0;
    for(int kt=0; kt<NKT; ++kt){
        if (kt+2 < NKT){ issue(kt+2, (kt+2)%3); cpwait<2>(); }
        else if (kt+1 < NKT){ cpwait<1>(); }
        else { cpwait<0>(); }
        __syncthreads();

        const uint32_t aH = aAddrB + (uint32_t)cb*BUFB;
        const uint32_t bB = bAddrB + (uint32_t)cb*BUFB + (uint32_t)NPROD*TSA;
        #pragma unroll
        for(int kf=0; kf<2; ++kf){
            uint32_t a4[4][4], b2[NF][2];
            #pragma unroll
            for(int mf=0; mf<4; ++mf) ldsm4(a4[mf], aH + (uint32_t)mf*1280u + (uint32_t)kf*32u);
            #pragma unroll
            for(int nf=0; nf<NF; ++nf) ldsm2(b2[nf], bB + (uint32_t)nf*640u + (uint32_t)kf*32u);
            #pragma unroll
            for(int mf=0; mf<4; ++mf)
                #pragma unroll
                for(int nf=0; nf<NF; ++nf) mma16816(acc[mf][nf], a4[mf], b2[nf]);   // Ah*B
            if (NPROD==2){
                #pragma unroll
                for(int mf=0; mf<4; ++mf) ldsm4(a4[mf], aH + TSA + (uint32_t)mf*1280u + (uint32_t)kf*32u);
                #pragma unroll
                for(int mf=0; mf<4; ++mf)
                    #pragma unroll
                    for(int nf=0; nf<NF; ++nf) mma16816(acc[mf][nf], a4[mf], b2[nf]);   // Al*B
            }
        }
        __syncthreads();
        cb = (cb+1)%3;
    }

    // ---------------- direct fragment epilogue ----------------
    const int qd = lane>>2, rr = lane&3;
    #pragma unroll
    for(int mf=0;mf<4;++mf){
        #pragma unroll
        for(int nf=0;nf<NF;++nf){
            const float* c = acc[mf][nf];
            const int mrow0 = m_w + mf*16 + qd;
            const int ncol  = n_w + nf*8 + rr*2;
            #pragma unroll
            for(int h2=0;h2<2;++h2){
                const int mloc = mrow0 + h2*8;
                float v0 = c[h2*2+0], v1 = c[h2*2+1];
                if (MODE==1){
                    const long rowg  = (long)bz*1048576 + (long)(m0+mloc)*1024 + n0 + ncol;
                    const long maskg = (long)bb*1048576 + (long)(m0+mloc)*1024 + n0 + ncol;
                    float2 bm = *reinterpret_cast<const float2*>(biasM + rowg);
                    float2 mk = *reinterpret_cast<const float2*>(maskM + maskg);
                    float2 o; o.x = v0 + bm.x + mk.x; o.y = v1 + bm.y + mk.y;
                    *reinterpret_cast<float2*>(outF + rowg) = o;
                } else if (MODE==2){
                    const int ng = n0 + ncol;
                    float2 o; o.x = v0 + bias1[ng]; o.y = v1 + bias1[ng+1];
                    *reinterpret_cast<float2*>(outF + (long)(m0+mloc)*768 + ng) = o;
                } else if (MODE==0){
                    const int ng = n0 + ncol;
                    v0 += bias1[ng]; v1 += bias1[ng+1];
                    if (n0 < 768){            // q: scaled, split hi/lo
                        v0 *= 0.125f; v1 *= 0.125f;
                        float h0,l0,h1,l1; split2(v0,h0,l0); split2(v1,h1,l1);
                        const long ob = (long)(m0+mloc)*768 + ng;
                        *reinterpret_cast<uint32_t*>(o1h+ob) = pack_h(h0,h1);
                        *reinterpret_cast<uint32_t*>(o1l+ob) = pack_h(l0,l1);
                    } else if (n0 < 1536){    // k: single fp16
                        const long ob = (long)(m0+mloc)*768 + ng - 768;
                        *reinterpret_cast<uint32_t*>(o2h+ob) = pack_h(v0,v1);
                    } else {                  // v: single fp16
                        const long ob = (long)(m0+mloc)*768 + ng - 1536;
                        *reinterpret_cast<uint32_t*>(o3h+ob) = pack_h(v0,v1);
                    }
                } else { // MODE 3: y split
                    float h0,l0,h1,l1; split2(v0,h0,l0); split2(v1,h1,l1);
                    const long ob = ((long)bb*1024 + m0 + mloc)*768 + hh*64 + ncol;
                    *reinterpret_cast<uint32_t*>(o1h+ob) = pack_h(h0,h1);
                    *reinterpret_cast<uint32_t*>(o1l+ob) = pack_h(l0,l1);
                }
            }
        }
    }
}

// softmax over 1024-wide rows: fp32 logits -> fp32 attn + fp16 attn (hi only)
__global__ __launch_bounds__(256) void softmax_kernel(const float* __restrict__ in, float* __restrict__ out,
                                                      half* __restrict__ oh){
    const long row = blockIdx.x;
    const int tid = threadIdx.x;
    __shared__ float sred[8];
    float4 v = *reinterpret_cast<const float4*>(in + row*1024 + tid*4);
    float m = fmaxf(fmaxf(v.x,v.y), fmaxf(v.z,v.w));
    #pragma unroll
    for(int o=16;o;o>>=1) m = fmaxf(m, __shfl_xor_sync(0xffffffffu,m,o));
    if((tid&31)==0) sred[tid>>5]=m;
    __syncthreads();
    float gm = sred[0];
    #pragma unroll
    for(int i=1;i<8;i++) gm = fmaxf(gm, sred[i]);
    __syncthreads();
    v.x=__expf(v.x-gm); v.y=__expf(v.y-gm); v.z=__expf(v.z-gm); v.w=__expf(v.w-gm);
    float s = v.x+v.y+v.z+v.w;
    #pragma unroll
    for(int o=16;o;o>>=1) s += __shfl_xor_sync(0xffffffffu,s,o);
    if((tid&31)==0) sred[tid>>5]=s;
    __syncthreads();
    float gs = sred[0];
    #pragma unroll
    for(int i=1;i<8;i++) gs += sred[i];
    const float inv = 1.0f/gs;
    v.x*=inv; v.y*=inv; v.z*=inv; v.w*=inv;
    *reinterpret_cast<float4*>(out + row*1024 + tid*4) = v;
    *reinterpret_cast<uint2*>(oh + row*1024 + tid*4) =
        make_uint2(pack_h(v.x,v.y), pack_h(v.z,v.w));
}

// fp32 -> fp16 hi/lo elementwise split
__global__ __launch_bounds__(256) void splitk(const float4* __restrict__ in,
                                              half* __restrict__ oh, half* __restrict__ ol, long n4){
    long i = (long)blockIdx.x*256 + threadIdx.x;
    if (i >= n4) return;
    float4 v = in[i];
    float h0,l0,h1,l1,h2,l2,h3,l3;
    split2(v.x,h0,l0); split2(v.y,h1,l1); split2(v.z,h2,l2); split2(v.w,h3,l3);
    *reinterpret_cast<uint2*>(oh + i*4) = make_uint2(pack_h(h0,h1), pack_h(h2,h3));
    *reinterpret_cast<uint2*>(ol + i*4) = make_uint2(pack_h(l0,l1), pack_h(l2,l3));
}

// W [K,N] fp32 -> Wt [N,K] single fp16
__global__ __launch_bounds__(256) void wtsplit(const float* __restrict__ W,
                                               half* __restrict__ oh, int K, int N){
    __shared__ float tf[32][33];
    const int n0 = blockIdx.x*32, k0 = blockIdx.y*32;
    const int tx = threadIdx.x&31, ty = threadIdx.x>>5;
    #pragma unroll
    for(int i=0;i<4;i++) tf[ty+8*i][tx] = W[(long)(k0+ty+8*i)*N + n0+tx];
    __syncthreads();
    #pragma unroll
    for(int i=0;i<4;i++){
        long o = (long)(n0+ty+8*i)*K + k0+tx;
        oh[o] = __float2half_rn(tf[tx][ty+8*i]);
    }
}

// v [B,T,H*64] -> vt [B*H, 64, 1024] single fp16
__global__ __launch_bounds__(256) void vtrans(const half* __restrict__ ih, half* __restrict__ oh){
    __shared__ half th[32][34];
    const int t0 = blockIdx.x*32, d0 = blockIdx.y*32, bz = blockIdx.z;
    const int bb = bz/H_, hh = bz - bb*H_;
    const int tx = threadIdx.x&31, ty = threadIdx.x>>5;
    const long ib = ((long)bb*1024 + t0)*768 + hh*64 + d0;
    #pragma unroll
    for(int i=0;i<4;i++) th[ty+8*i][tx] = ih[ib + (long)(ty+8*i)*768 + tx];
    __syncthreads();
    const long ob = ((long)bz*64 + d0)*1024 + t0;
    #pragma unroll
    for(int i=0;i<4;i++) oh[ob + (long)(ty+8*i)*1024 + tx] = th[tx][ty+8*i];
}

extern "C" void kernel_launch(void* const* d_in, const int* in_sizes, int n_in,
                              void* d_out, int out_size)
{
    const float* x     = (const float*)d_in[0];
    const float* mask  = (const float*)d_in[1];
    const float* bias  = (const float*)d_in[2];
    const float* Wqkv  = (const float*)d_in[3];
    const float* bqkv  = (const float*)d_in[4];
    const float* Wproj = (const float*)d_in[5];
    const float* bproj = (const float*)d_in[6];
    float* out = (float*)d_out;

    half *xh,*xl,*wq,*wp,*qh,*ql,*kk,*vv,*vt,*ah,*yh,*yl;
    float *logits;
    cudaGetSymbolAddress((void**)&xh,g_xh);   cudaGetSymbolAddress((void**)&xl,g_xl);
    cudaGetSymbolAddress((void**)&wq,g_wq);   cudaGetSymbolAddress((void**)&wp,g_wp);
    cudaGetSymbolAddress((void**)&qh,g_qh);   cudaGetSymbolAddress((void**)&ql,g_ql);
    cudaGetSymbolAddress((void**)&kk,g_kk);   cudaGetSymbolAddress((void**)&vv,g_vv);
    cudaGetSymbolAddress((void**)&vt,g_vt);
    cudaGetSymbolAddress((void**)&ah,g_ah);
    cudaGetSymbolAddress((void**)&yh,g_yh);   cudaGetSymbolAddress((void**)&yl,g_yl);
    cudaGetSymbolAddress((void**)&logits,g_logits);

    float* attn = ((long)out_size >= YN + AN) ? (out + YN) : logits;

    const int smemBig = 92160;   // 3*(2*10240 + 10240)
    const int smemAV  = 46080;   // 3*(10240 + 5120)
    cudaFuncSetAttribute(gemm_tc<0>, cudaFuncAttributeMaxDynamicSharedMemorySize, smemBig);
    cudaFuncSetAttribute(gemm_tc<1>, cudaFuncAttributeMaxDynamicSharedMemorySize, smemBig);
    cudaFuncSetAttribute(gemm_tc<2>, cudaFuncAttributeMaxDynamicSharedMemorySize, smemBig);
    cudaFuncSetAttribute(gemm_tc<3>, cudaFuncAttributeMaxDynamicSharedMemorySize, smemAV);

    // 1) split x into fp16 hi/lo
    splitk<<<(YN/4+255)/256, 256>>>((const float4*)x, xh, xl, YN/4);
    // 2) transpose weights to [N,K] single fp16
    wtsplit<<<dim3(2304/32, 768/32), 256>>>(Wqkv, wq, 768, 2304);
    wtsplit<<<dim3(768/32, 768/32),  256>>>(Wproj, wp, 768, 768);
    // 3) qkv GEMM -> q(scaled, split) / k / v
    gemm_tc<0><<<dim3(18,32,1), 256, smemBig>>>(xh, xl, wq, bqkv, nullptr, nullptr, nullptr,
                                                qh, ql, kk, vv);
    // 4) transpose v -> [B*H,64,1024]
    vtrans<<<dim3(32,2,48), 256>>>(vv, vt);
    // 5) logits fp32 = q k^T + bias + mask
    gemm_tc<1><<<dim3(8,8,48), 256, smemBig>>>(qh, ql, kk, nullptr, bias, mask, logits,
                                               nullptr, nullptr, nullptr, nullptr);
    // 6) softmax -> attn fp32 + attn fp16 (hi only)
    softmax_kernel<<<48*1024, 256>>>(logits, attn, ah);
    // 7) y = attn @ v^T (single-product A)
    gemm_tc<3><<<dim3(1,8,48), 256, smemAV>>>(ah, nullptr, vt, nullptr, nullptr, nullptr, nullptr,
                                              yh, yl, nullptr, nullptr);
    // 8) out = y @ Wproj + bproj
    gemm_tc<2><<<dim3(6,32,1), 256, smemBig>>>(yh, yl, wp, bproj, nullptr, nullptr, out,
                                               nullptr, nullptr, nullptr, nullptr);
}

// round 14
// speedup vs baseline: 1.5038x; 1.0528x over previous
#include <cuda_runtime.h>
#include <cuda_fp16.h>
#include <cstdint>

static constexpr int B_=4, T_=1024, C_=768, H_=12;
static constexpr long BT=4096, YN=BT*C_, AN=48L*1024*1024;

__device__ __align__(1024) half g_xh[YN], g_xl[YN];
__device__ __align__(1024) half g_wq[2304L*768];
__device__ __align__(1024) half g_wp[768L*768];
__device__ __align__(1024) half g_qh[YN], g_ql[YN];
__device__ __align__(1024) half g_kk[YN];
__device__ __align__(1024) half g_vv[YN], g_vt[YN];
__device__ __align__(1024) float g_logits[AN];
__device__ __align__(1024) half g_ah[AN];             // normalized attn (fp16)
__device__ __align__(1024) half g_yy[YN];             // y (fp16, single)

// ---------------- helpers ----------------
__device__ __forceinline__ uint32_t smem_u32(const void* p){
    uint32_t a; asm("{ .reg .u64 t; cvta.to.shared.u64 t, %1; cvt.u32.u64 %0, t; }":"=r"(a):"l"(p)); return a;
}
__device__ __forceinline__ void mma16816(float* c, const uint32_t* a, const uint32_t* b){
    asm volatile("mma.sync.aligned.m16n8k16.row.col.f32.f16.f16.f32 "
        "{%0,%1,%2,%3}, {%4,%5,%6,%7}, {%8,%9}, {%0,%1,%2,%3};"
        : "+f"(c[0]),"+f"(c[1]),"+f"(c[2]),"+f"(c[3])
        : "r"(a[0]),"r"(a[1]),"r"(a[2]),"r"(a[3]),"r"(b[0]),"r"(b[1]));
}
__device__ __forceinline__ void ldsm4(uint32_t* r, uint32_t addr){
    asm volatile("ldmatrix.sync.aligned.m8n8.x4.shared.b16 {%0,%1,%2,%3}, [%4];"
        : "=r"(r[0]),"=r"(r[1]),"=r"(r[2]),"=r"(r[3]) : "r"(addr));
}
__device__ __forceinline__ void ldsm2(uint32_t* r, uint32_t addr){
    asm volatile("ldmatrix.sync.aligned.m8n8.x2.shared.b16 {%0,%1}, [%2];"
        : "=r"(r[0]),"=r"(r[1]) : "r"(addr));
}
__device__ __forceinline__ void cpasync16(uint32_t dst, const void* src){
    asm volatile("cp.async.cg.shared.global [%0], [%1], 16;" :: "r"(dst), "l"(src));
}
__device__ __forceinline__ void cpcommit(){ asm volatile("cp.async.commit_group;" ::: "memory"); }
template<int N> __device__ __forceinline__ void cpwait(){ asm volatile("cp.async.wait_group %0;" :: "n"(N) : "memory"); }
__device__ __forceinline__ uint32_t pack_h(float a, float b){
    half2 t = __floats2half2_rn(a,b);
    return *reinterpret_cast<uint32_t*>(&t);
}
__device__ __forceinline__ void split2(float v, float& h, float& l){
    half hb = __float2half_rn(v); h = __half2float(hb); l = v - h;
}

// ---------------------------------------------------------------------------
// TN-form fp16 tensor-core GEMM. A split hi/lo (2 products) for MODE 0/1;
// single-product A for MODE 2 (proj, y fp16) and MODE 3 (AV, attn fp16).
// 3-stage cp.async pipeline. A:[M,K], B:[N,K]; C = A*B^T fp32.
// MODE 0:qkv  1:logits(fp32)  2:proj  3:AV
// ---------------------------------------------------------------------------
template<int MODE>
__global__ __launch_bounds__(256)
void gemm_tc(const half* __restrict__ Ah, const half* __restrict__ Al,
             const half* __restrict__ Bs,
             const float* __restrict__ bias1, const float* __restrict__ biasM,
             const float* __restrict__ maskM, float* __restrict__ outF,
             half* __restrict__ o1h, half* __restrict__ o1l,
             half* __restrict__ o2h, half* __restrict__ o3h)
{
    constexpr int TN  = (MODE==3)?64:128;
    constexpr int NF  = TN/32;
    constexpr int NPROD = (MODE>=2)?1:2;       // A-side products
    constexpr int KT  = (MODE==1)?64:((MODE==3)?1024:768);
    constexpr long LDA = (MODE==3)?1024:768;
    constexpr long LDB = (MODE==3)?1024:768;
    constexpr int NKT = KT/32;
    constexpr uint32_t TSA  = 10240u;          // 128x32 fp16 tile, 80B pitch
    constexpr uint32_t TSB  = TN*80u;
    constexpr uint32_t BUFB = (uint32_t)NPROD*TSA + TSB;

    extern __shared__ half smem[];
    const uint32_t sb0 = smem_u32(smem);

    const int tid = threadIdx.x, wid = tid>>5, lane = tid&31;
    const int wr = wid>>2, wc = wid&3;
    const int m_w = wr*64, n_w = wc*(TN/4);
    const int m0 = blockIdx.y*128, n0 = blockIdx.x*TN;
    const int bz = blockIdx.z, bb = bz/H_, hh = bz - bb*H_;

    long aOff, bOff;
    if (MODE==1){ aOff = ((long)bb*1024 + m0)*768 + hh*64; bOff = ((long)bb*1024 + n0)*768 + hh*64; }
    else if (MODE==3){ aOff = (long)bz*1048576 + (long)m0*1024; bOff = (long)bz*65536; }
    else { aOff = (long)m0*LDA; bOff = (long)n0*LDB; }
    const half *pAh=Ah+aOff, *pAl=(NPROD==2)?(Al+aOff):nullptr, *pB=Bs+bOff;

    float acc[4][NF][4];
    #pragma unroll
    for(int i=0;i<4;i++)
        #pragma unroll
        for(int j=0;j<NF;j++)
            #pragma unroll
            for(int k=0;k<4;k++) acc[i][j][k]=0.f;

    const uint32_t aAddrB = sb0 + (uint32_t)(m_w + (lane&15))*80u + (uint32_t)(lane>>4)*16u;
    const uint32_t bAddrB = sb0 + (uint32_t)(n_w + (lane&7))*80u + (uint32_t)((lane>>3)&1)*16u;

    auto issue = [&](int kt, int buf){
        const long k0 = (long)kt*32;
        const uint32_t base = sb0 + (uint32_t)buf*BUFB;
        #pragma unroll
        for(int it=0; it<2*NPROD; ++it){           // A tiles: 512 chunks per product
            const int i = tid + it*256;
            const int t = i>>9, j = i&511, r = j>>2, c = j&3;
            const half* src = (t? pAl : pAh) + (long)r*LDA + k0 + c*8;
            cpasync16(base + (uint32_t)t*TSA + (uint32_t)(r*80 + c*16), src);
        }
        #pragma unroll
        for(int it=0; it<TN/64; ++it){             // B single: TN*4 x 16B
            const int i = tid + it*256;
            const int r = i>>2, c = i&3;
            const half* src = pB + (long)r*LDB + k0 + c*8;
            cpasync16(base + (uint32_t)NPROD*TSA + (uint32_t)(r*80 + c*16), src);
        }
        cpcommit();
    };

    // 3-stage prologue
    issue(0, 0);
    if (NKT > 1) issue(1, 1);

    int cb = 0;
    for(int kt=0; kt<NKT; ++kt){
        if (kt+2 < NKT){ issue(kt+2, (kt+2)%3); cpwait<2>(); }
        else if (kt+1 < NKT){ cpwait<1>(); }
        else { cpwait<0>(); }
        __syncthreads();

        const uint32_t aH = aAddrB + (uint32_t)cb*BUFB;
        const uint32_t bB = bAddrB + (uint32_t)cb*BUFB + (uint32_t)NPROD*TSA;
        #pragma unroll
        for(int kf=0; kf<2; ++kf){
            uint32_t a4[4][4], b2[NF][2];
            #pragma unroll
            for(int mf=0; mf<4; ++mf) ldsm4(a4[mf], aH + (uint32_t)mf*1280u + (uint32_t)kf*32u);
            #pragma unroll
            for(int nf=0; nf<NF; ++nf) ldsm2(b2[nf], bB + (uint32_t)nf*640u + (uint32_t)kf*32u);
            #pragma unroll
            for(int mf=0; mf<4; ++mf)
                #pragma unroll
                for(int nf=0; nf<NF; ++nf) mma16816(acc[mf][nf], a4[mf], b2[nf]);   // Ah*B
            if (NPROD==2){
                #pragma unroll
                for(int mf=0; mf<4; ++mf) ldsm4(a4[mf], aH + TSA + (uint32_t)mf*1280u + (uint32_t)kf*32u);
                #pragma unroll
                for(int mf=0; mf<4; ++mf)
                    #pragma unroll
                    for(int nf=0; nf<NF; ++nf) mma16816(acc[mf][nf], a4[mf], b2[nf]);   // Al*B
            }
        }
        __syncthreads();
        cb = (cb+1)%3;
    }

    // ---------------- direct fragment epilogue ----------------
    const int qd = lane>>2, rr = lane&3;
    #pragma unroll
    for(int mf=0;mf<4;++mf){
        #pragma unroll
        for(int nf=0;nf<NF;++nf){
            const float* c = acc[mf][nf];
            const int mrow0 = m_w + mf*16 + qd;
            const int ncol  = n_w + nf*8 + rr*2;
            #pragma unroll
            for(int h2=0;h2<2;++h2){
                const int mloc = mrow0 + h2*8;
                float v0 = c[h2*2+0], v1 = c[h2*2+1];
                if (MODE==1){
                    const long rowg  = (long)bz*1048576 + (long)(m0+mloc)*1024 + n0 + ncol;
                    const long maskg = (long)bb*1048576 + (long)(m0+mloc)*1024 + n0 + ncol;
                    float2 bm = *reinterpret_cast<const float2*>(biasM + rowg);
                    float2 mk = *reinterpret_cast<const float2*>(maskM + maskg);
                    float2 o; o.x = v0 + bm.x + mk.x; o.y = v1 + bm.y + mk.y;
                    *reinterpret_cast<float2*>(outF + rowg) = o;
                } else if (MODE==2){
                    const int ng = n0 + ncol;
                    float2 o; o.x = v0 + bias1[ng]; o.y = v1 + bias1[ng+1];
                    *reinterpret_cast<float2*>(outF + (long)(m0+mloc)*768 + ng) = o;
                } else if (MODE==0){
                    const int ng = n0 + ncol;
                    v0 += bias1[ng]; v1 += bias1[ng+1];
                    if (n0 < 768){            // q: scaled, split hi/lo
                        v0 *= 0.125f; v1 *= 0.125f;
                        float h0,l0,h1,l1; split2(v0,h0,l0); split2(v1,h1,l1);
                        const long ob = (long)(m0+mloc)*768 + ng;
                        *reinterpret_cast<uint32_t*>(o1h+ob) = pack_h(h0,h1);
                        *reinterpret_cast<uint32_t*>(o1l+ob) = pack_h(l0,l1);
                    } else if (n0 < 1536){    // k: single fp16
                        const long ob = (long)(m0+mloc)*768 + ng - 768;
                        *reinterpret_cast<uint32_t*>(o2h+ob) = pack_h(v0,v1);
                    } else {                  // v: single fp16
                        const long ob = (long)(m0+mloc)*768 + ng - 1536;
                        *reinterpret_cast<uint32_t*>(o3h+ob) = pack_h(v0,v1);
                    }
                } else { // MODE 3: y single fp16
                    const long ob = ((long)bb*1024 + m0 + mloc)*768 + hh*64 + ncol;
                    *reinterpret_cast<uint32_t*>(o1h+ob) = pack_h(v0,v1);
                }
            }
        }
    }
}

// softmax over 1024-wide rows: fp32 logits -> fp32 attn + fp16 attn
__global__ __launch_bounds__(256) void softmax_kernel(const float* __restrict__ in, float* __restrict__ out,
                                                      half* __restrict__ oh){
    const long row = blockIdx.x;
    const int tid = threadIdx.x;
    __shared__ float sred[8];
    float4 v = *reinterpret_cast<const float4*>(in + row*1024 + tid*4);
    float m = fmaxf(fmaxf(v.x,v.y), fmaxf(v.z,v.w));
    #pragma unroll
    for(int o=16;o;o>>=1) m = fmaxf(m, __shfl_xor_sync(0xffffffffu,m,o));
    if((tid&31)==0) sred[tid>>5]=m;
    __syncthreads();
    float gm = sred[0];
    #pragma unroll
    for(int i=1;i<8;i++) gm = fmaxf(gm, sred[i]);
    __syncthreads();
    v.x=__expf(v.x-gm); v.y=__expf(v.y-gm); v.z=__expf(v.z-gm); v.w=__expf(v.w-gm);
    float s = v.x+v.y+v.z+v.w;
    #pragma unroll
    for(int o=16;o;o>>=1) s += __shfl_xor_sync(0xffffffffu,s,o);
    if((tid&31)==0) sred[tid>>5]=s;
    __syncthreads();
    float gs = sred[0];
    #pragma unroll
    for(int i=1;i<8;i++) gs += sred[i];
    const float inv = 1.0f/gs;
    v.x*=inv; v.y*=inv; v.z*=inv; v.w*=inv;
    *reinterpret_cast<float4*>(out + row*1024 + tid*4) = v;
    *reinterpret_cast<uint2*>(oh + row*1024 + tid*4) =
        make_uint2(pack_h(v.x,v.y), pack_h(v.z,v.w));
}

// fp32 -> fp16 hi/lo elementwise split
__global__ __launch_bounds__(256) void splitk(const float4* __restrict__ in,
                                              half* __restrict__ oh, half* __restrict__ ol, long n4){
    long i = (long)blockIdx.x*256 + threadIdx.x;
    if (i >= n4) return;
    float4 v = in[i];
    float h0,l0,h1,l1,h2,l2,h3,l3;
    split2(v.x,h0,l0); split2(v.y,h1,l1); split2(v.z,h2,l2); split2(v.w,h3,l3);
    *reinterpret_cast<uint2*>(oh + i*4) = make_uint2(pack_h(h0,h1), pack_h(h2,h3));
    *reinterpret_cast<uint2*>(ol + i*4) = make_uint2(pack_h(l0,l1), pack_h(l2,l3));
}

// W [K,N] fp32 -> Wt [N,K] single fp16
__global__ __launch_bounds__(256) void wtsplit(const float* __restrict__ W,
                                               half* __restrict__ oh, int K, int N){
    __shared__ float tf[32][33];
    const int n0 = blockIdx.x*32, k0 = blockIdx.y*32;
    const int tx = threadIdx.x&31, ty = threadIdx.x>>5;
    #pragma unroll
    for(int i=0;i<4;i++) tf[ty+8*i][tx] = W[(long)(k0+ty+8*i)*N + n0+tx];
    __syncthreads();
    #pragma unroll
    for(int i=0;i<4;i++){
        long o = (long)(n0+ty+8*i)*K + k0+tx;
        oh[o] = __float2half_rn(tf[tx][ty+8*i]);
    }
}

// v [B,T,H*64] -> vt [B*H, 64, 1024] single fp16
__global__ __launch_bounds__(256) void vtrans(const half* __restrict__ ih, half* __restrict__ oh){
    __shared__ half th[32][34];
    const int t0 = blockIdx.x*32, d0 = blockIdx.y*32, bz = blockIdx.z;
    const int bb = bz/H_, hh = bz - bb*H_;
    const int tx = threadIdx.x&31, ty = threadIdx.x>>5;
    const long ib = ((long)bb*1024 + t0)*768 + hh*64 + d0;
    #pragma unroll
    for(int i=0;i<4;i++) th[ty+8*i][tx] = ih[ib + (long)(ty+8*i)*768 + tx];
    __syncthreads();
    const long ob = ((long)bz*64 + d0)*1024 + t0;
    #pragma unroll
    for(int i=0;i<4;i++) oh[ob + (long)(ty+8*i)*1024 + tx] = th[tx][ty+8*i];
}

extern "C" void kernel_launch(void* const* d_in, const int* in_sizes, int n_in,
                              void* d_out, int out_size)
{
    const float* x     = (const float*)d_in[0];
    const float* mask  = (const float*)d_in[1];
    const float* bias  = (const float*)d_in[2];
    const float* Wqkv  = (const float*)d_in[3];
    const float* bqkv  = (const float*)d_in[4];
    const float* Wproj = (const float*)d_in[5];
    const float* bproj = (const float*)d_in[6];
    float* out = (float*)d_out;

    half *xh,*xl,*wq,*wp,*qh,*ql,*kk,*vv,*vt,*ah,*yy;
    float *logits;
    cudaGetSymbolAddress((void**)&xh,g_xh);   cudaGetSymbolAddress((void**)&xl,g_xl);
    cudaGetSymbolAddress((void**)&wq,g_wq);   cudaGetSymbolAddress((void**)&wp,g_wp);
    cudaGetSymbolAddress((void**)&qh,g_qh);   cudaGetSymbolAddress((void**)&ql,g_ql);
    cudaGetSymbolAddress((void**)&kk,g_kk);   cudaGetSymbolAddress((void**)&vv,g_vv);
    cudaGetSymbolAddress((void**)&vt,g_vt);
    cudaGetSymbolAddress((void**)&ah,g_ah);   cudaGetSymbolAddress((void**)&yy,g_yy);
    cudaGetSymbolAddress((void**)&logits,g_logits);

    float* attn = ((long)out_size >= YN + AN) ? (out + YN) : logits;

    const int smemBig   = 92160;   // MODE 0/1: 3*(2*10240 + 10240)
    const int smemProj  = 61440;   // MODE 2:   3*(10240 + 10240)
    const int smemAV    = 46080;   // MODE 3:   3*(10240 + 5120)
    cudaFuncSetAttribute(gemm_tc<0>, cudaFuncAttributeMaxDynamicSharedMemorySize, smemBig);
    cudaFuncSetAttribute(gemm_tc<1>, cudaFuncAttributeMaxDynamicSharedMemorySize, smemBig);
    cudaFuncSetAttribute(gemm_tc<2>, cudaFuncAttributeMaxDynamicSharedMemorySize, smemProj);
    cudaFuncSetAttribute(gemm_tc<3>, cudaFuncAttributeMaxDynamicSharedMemorySize, smemAV);

    // 1) split x into fp16 hi/lo
    splitk<<<(YN/4+255)/256, 256>>>((const float4*)x, xh, xl, YN/4);
    // 2) transpose weights to [N,K] single fp16
    wtsplit<<<dim3(2304/32, 768/32), 256>>>(Wqkv, wq, 768, 2304);
    wtsplit<<<dim3(768/32, 768/32),  256>>>(Wproj, wp, 768, 768);
    // 3) qkv GEMM -> q(scaled, split) / k / v
    gemm_tc<0><<<dim3(18,32,1), 256, smemBig>>>(xh, xl, wq, bqkv, nullptr, nullptr, nullptr,
                                                qh, ql, kk, vv);
    // 4) transpose v -> [B*H,64,1024]
    vtrans<<<dim3(32,2,48), 256>>>(vv, vt);
    // 5) logits fp32 = q k^T + bias + mask
    gemm_tc<1><<<dim3(8,8,48), 256, smemBig>>>(qh, ql, kk, nullptr, bias, mask, logits,
                                               nullptr, nullptr, nullptr, nullptr);
    // 6) softmax -> attn fp32 + attn fp16
    softmax_kernel<<<48*1024, 256>>>(logits, attn, ah);
    // 7) y = attn @ v^T (single-product, single fp16 output)
    gemm_tc<3><<<dim3(1,8,48), 256, smemAV>>>(ah, nullptr, vt, nullptr, nullptr, nullptr, nullptr,
                                              yy, nullptr, nullptr, nullptr);
    // 8) out = y @ Wproj + bproj (single-product)
    gemm_tc<2><<<dim3(6,32,1), 256, smemProj>>>(yy, nullptr, wp, bproj, nullptr, nullptr, out,
                                                nullptr, nullptr, nullptr, nullptr);
}

// round 15
// speedup vs baseline: 1.5212x; 1.0116x over previous
#include <cuda_runtime.h>
#include <cuda_fp16.h>
#include <cstdint>

static constexpr int B_=4, T_=1024, C_=768, H_=12;
static constexpr long BT=4096, YN=BT*C_, AN=48L*1024*1024;

__device__ __align__(1024) half g_xh[YN], g_xl[YN];
__device__ __align__(1024) half g_wq[2304L*768];
__device__ __align__(1024) half g_wp[768L*768];
__device__ __align__(1024) half g_qh[YN], g_ql[YN];
__device__ __align__(1024) half g_kk[YN];
__device__ __align__(1024) half g_vv[YN], g_vt[YN];
__device__ __align__(1024) float g_logits[AN];
__device__ __align__(1024) half g_ah[AN];             // normalized attn (fp16)
__device__ __align__(1024) half g_yy[YN];             // y (fp16, single)

// ---------------- helpers ----------------
__device__ __forceinline__ uint32_t smem_u32(const void* p){
    uint32_t a; asm("{ .reg .u64 t; cvta.to.shared.u64 t, %1; cvt.u32.u64 %0, t; }":"=r"(a):"l"(p)); return a;
}
__device__ __forceinline__ void mma16816(float* c, const uint32_t* a, const uint32_t* b){
    asm volatile("mma.sync.aligned.m16n8k16.row.col.f32.f16.f16.f32 "
        "{%0,%1,%2,%3}, {%4,%5,%6,%7}, {%8,%9}, {%0,%1,%2,%3};"
        : "+f"(c[0]),"+f"(c[1]),"+f"(c[2]),"+f"(c[3])
        : "r"(a[0]),"r"(a[1]),"r"(a[2]),"r"(a[3]),"r"(b[0]),"r"(b[1]));
}
__device__ __forceinline__ void ldsm4(uint32_t* r, uint32_t addr){
    asm volatile("ldmatrix.sync.aligned.m8n8.x4.shared.b16 {%0,%1,%2,%3}, [%4];"
        : "=r"(r[0]),"=r"(r[1]),"=r"(r[2]),"=r"(r[3]) : "r"(addr));
}
__device__ __forceinline__ void cpasync16(uint32_t dst, const void* src){
    asm volatile("cp.async.cg.shared.global [%0], [%1], 16;" :: "r"(dst), "l"(src));
}
__device__ __forceinline__ void cpcommit(){ asm volatile("cp.async.commit_group;" ::: "memory"); }
template<int N> __device__ __forceinline__ void cpwait(){ asm volatile("cp.async.wait_group %0;" :: "n"(N) : "memory"); }
__device__ __forceinline__ uint32_t pack_h(float a, float b){
    half2 t = __floats2half2_rn(a,b);
    return *reinterpret_cast<uint32_t*>(&t);
}
__device__ __forceinline__ void split2(float v, float& h, float& l){
    half hb = __float2half_rn(v); h = __half2float(hb); l = v - h;
}

// ---------------------------------------------------------------------------
// TN-form fp16 tensor-core GEMM. A split hi/lo (2 products) for MODE 0/1;
// single-product A for MODE 2 (proj) and MODE 3 (AV). 3-stage cp.async
// pipeline with ONE sync per K-tile; B fragments for both kf per ldsm4.
// A:[M,K], B:[N,K]; C = A*B^T fp32.
// MODE 0:qkv  1:logits(fp32)  2:proj  3:AV
// ---------------------------------------------------------------------------
template<int MODE>
__global__ __launch_bounds__(256)
void gemm_tc(const half* __restrict__ Ah, const half* __restrict__ Al,
             const half* __restrict__ Bs,
             const float* __restrict__ bias1, const float* __restrict__ biasM,
             const float* __restrict__ maskM, float* __restrict__ outF,
             half* __restrict__ o1h, half* __restrict__ o1l,
             half* __restrict__ o2h, half* __restrict__ o3h)
{
    constexpr int TN  = (MODE==3)?64:128;
    constexpr int NF  = TN/32;
    constexpr int NPROD = (MODE>=2)?1:2;       // A-side products
    constexpr int KT  = (MODE==1)?64:((MODE==3)?1024:768);
    constexpr long LDA = (MODE==3)?1024:768;
    constexpr long LDB = (MODE==3)?1024:768;
    constexpr int NKT = KT/32;
    constexpr uint32_t TSA  = 10240u;          // 128x32 fp16 tile, 80B pitch
    constexpr uint32_t TSB  = TN*80u;
    constexpr uint32_t BUFB = (uint32_t)NPROD*TSA + TSB;

    extern __shared__ half smem[];
    const uint32_t sb0 = smem_u32(smem);

    const int tid = threadIdx.x, wid = tid>>5, lane = tid&31;
    const int wr = wid>>2, wc = wid&3;
    const int m_w = wr*64, n_w = wc*(TN/4);
    const int m0 = blockIdx.y*128, n0 = blockIdx.x*TN;
    const int bz = blockIdx.z, bb = bz/H_, hh = bz - bb*H_;

    long aOff, bOff;
    if (MODE==1){ aOff = ((long)bb*1024 + m0)*768 + hh*64; bOff = ((long)bb*1024 + n0)*768 + hh*64; }
    else if (MODE==3){ aOff = (long)bz*1048576 + (long)m0*1024; bOff = (long)bz*65536; }
    else { aOff = (long)m0*LDA; bOff = (long)n0*LDB; }
    const half *pAh=Ah+aOff, *pAl=(NPROD==2)?(Al+aOff):nullptr, *pB=Bs+bOff;

    float acc[4][NF][4];
    #pragma unroll
    for(int i=0;i<4;i++)
        #pragma unroll
        for(int j=0;j<NF;j++)
            #pragma unroll
            for(int k=0;k<4;k++) acc[i][j][k]=0.f;

    const uint32_t aAddrB = sb0 + (uint32_t)(m_w + (lane&15))*80u + (uint32_t)(lane>>4)*16u;
    // B: 4 lane-groups cover k-bytes 0..64 => one ldsm4 gives both kf halves
    const uint32_t bAddrB = sb0 + (uint32_t)(n_w + (lane&7))*80u + (uint32_t)((lane>>3)&3)*16u;

    auto issue = [&](int kt, int buf){
        const long k0 = (long)kt*32;
        const uint32_t base = sb0 + (uint32_t)buf*BUFB;
        #pragma unroll
        for(int it=0; it<2*NPROD; ++it){           // A tiles: 512 chunks per product
            const int i = tid + it*256;
            const int t = i>>9, j = i&511, r = j>>2, c = j&3;
            const half* src = (t? pAl : pAh) + (long)r*LDA + k0 + c*8;
            cpasync16(base + (uint32_t)t*TSA + (uint32_t)(r*80 + c*16), src);
        }
        #pragma unroll
        for(int it=0; it<TN/64; ++it){             // B single: TN*4 x 16B
            const int i = tid + it*256;
            const int r = i>>2, c = i&3;
            const half* src = pB + (long)r*LDB + k0 + c*8;
            cpasync16(base + (uint32_t)NPROD*TSA + (uint32_t)(r*80 + c*16), src);
        }
        cpcommit();
    };

    // 3-stage prologue
    issue(0, 0);
    if (NKT > 1) issue(1, 1);

    int cb = 0;
    for(int kt=0; kt<NKT; ++kt){
        if (kt+1 < NKT) cpwait<1>(); else cpwait<0>();
        __syncthreads();

        const uint32_t aH = aAddrB + (uint32_t)cb*BUFB;
        const uint32_t bB = bAddrB + (uint32_t)cb*BUFB + (uint32_t)NPROD*TSA;

        uint32_t b4[NF][4];
        #pragma unroll
        for(int nf=0; nf<NF; ++nf) ldsm4(b4[nf], bB + (uint32_t)nf*640u);

        #pragma unroll
        for(int kf=0; kf<2; ++kf){
            uint32_t a4[4][4];
            #pragma unroll
            for(int mf=0; mf<4; ++mf) ldsm4(a4[mf], aH + (uint32_t)mf*1280u + (uint32_t)kf*32u);
            #pragma unroll
            for(int mf=0; mf<4; ++mf)
                #pragma unroll
                for(int nf=0; nf<NF; ++nf) mma16816(acc[mf][nf], a4[mf], &b4[nf][2*kf]);   // Ah*B
            if (NPROD==2){
                #pragma unroll
                for(int mf=0; mf<4; ++mf) ldsm4(a4[mf], aH + TSA + (uint32_t)mf*1280u + (uint32_t)kf*32u);
                #pragma unroll
                for(int mf=0; mf<4; ++mf)
                    #pragma unroll
                    for(int nf=0; nf<NF; ++nf) mma16816(acc[mf][nf], a4[mf], &b4[nf][2*kf]);   // Al*B
            }
        }
        // issue next tile AFTER compute: writes buf (kt+2)%3 == (kt-1)%3, which
        // every warp finished reading before this iteration's barrier.
        if (kt+2 < NKT) issue(kt+2, (kt+2)%3);
        cb = (cb+1)%3;
    }

    // ---------------- direct fragment epilogue ----------------
    const int qd = lane>>2, rr = lane&3;
    #pragma unroll
    for(int mf=0;mf<4;++mf){
        #pragma unroll
        for(int nf=0;nf<NF;++nf){
            const float* c = acc[mf][nf];
            const int mrow0 = m_w + mf*16 + qd;
            const int ncol  = n_w + nf*8 + rr*2;
            #pragma unroll
            for(int h2=0;h2<2;++h2){
                const int mloc = mrow0 + h2*8;
                float v0 = c[h2*2+0], v1 = c[h2*2+1];
                if (MODE==1){
                    const long rowg  = (long)bz*1048576 + (long)(m0+mloc)*1024 + n0 + ncol;
                    const long maskg = (long)bb*1048576 + (long)(m0+mloc)*1024 + n0 + ncol;
                    float2 bm = *reinterpret_cast<const float2*>(biasM + rowg);
                    float2 mk = *reinterpret_cast<const float2*>(maskM + maskg);
                    float2 o; o.x = v0 + bm.x + mk.x; o.y = v1 + bm.y + mk.y;
                    *reinterpret_cast<float2*>(outF + rowg) = o;
                } else if (MODE==2){
                    const int ng = n0 + ncol;
                    float2 o; o.x = v0 + bias1[ng]; o.y = v1 + bias1[ng+1];
                    *reinterpret_cast<float2*>(outF + (long)(m0+mloc)*768 + ng) = o;
                } else if (MODE==0){
                    const int ng = n0 + ncol;
                    v0 += bias1[ng]; v1 += bias1[ng+1];
                    if (n0 < 768){            // q: scaled, split hi/lo
                        v0 *= 0.125f; v1 *= 0.125f;
                        float h0,l0,h1,l1; split2(v0,h0,l0); split2(v1,h1,l1);
                        const long ob = (long)(m0+mloc)*768 + ng;
                        *reinterpret_cast<uint32_t*>(o1h+ob) = pack_h(h0,h1);
                        *reinterpret_cast<uint32_t*>(o1l+ob) = pack_h(l0,l1);
                    } else if (n0 < 1536){    // k: single fp16
                        const long ob = (long)(m0+mloc)*768 + ng - 768;
                        *reinterpret_cast<uint32_t*>(o2h+ob) = pack_h(v0,v1);
                    } else {                  // v: single fp16
                        const long ob = (long)(m0+mloc)*768 + ng - 1536;
                        *reinterpret_cast<uint32_t*>(o3h+ob) = pack_h(v0,v1);
                    }
                } else { // MODE 3: y single fp16
                    const long ob = ((long)bb*1024 + m0 + mloc)*768 + hh*64 + ncol;
                    *reinterpret_cast<uint32_t*>(o1h+ob) = pack_h(v0,v1);
                }
            }
        }
    }
}

// softmax over 1024-wide rows: fp32 logits -> fp32 attn + fp16 attn
__global__ __launch_bounds__(256) void softmax_kernel(const float* __restrict__ in, float* __restrict__ out,
                                                      half* __restrict__ oh){
    const long row = blockIdx.x;
    const int tid = threadIdx.x;
    __shared__ float sred[8];
    float4 v = *reinterpret_cast<const float4*>(in + row*1024 + tid*4);
    float m = fmaxf(fmaxf(v.x,v.y), fmaxf(v.z,v.w));
    #pragma unroll
    for(int o=16;o;o>>=1) m = fmaxf(m, __shfl_xor_sync(0xffffffffu,m,o));
    if((tid&31)==0) sred[tid>>5]=m;
    __syncthreads();
    float gm = sred[0];
    #pragma unroll
    for(int i=1;i<8;i++) gm = fmaxf(gm, sred[i]);
    __syncthreads();
    v.x=__expf(v.x-gm); v.y=__expf(v.y-gm); v.z=__expf(v.z-gm); v.w=__expf(v.w-gm);
    float s = v.x+v.y+v.z+v.w;
    #pragma unroll
    for(int o=16;o;o>>=1) s += __shfl_xor_sync(0xffffffffu,s,o);
    if((tid&31)==0) sred[tid>>5]=s;
    __syncthreads();
    float gs = sred[0];
    #pragma unroll
    for(int i=1;i<8;i++) gs += sred[i];
    const float inv = 1.0f/gs;
    v.x*=inv; v.y*=inv; v.z*=inv; v.w*=inv;
    *reinterpret_cast<float4*>(out + row*1024 + tid*4) = v;
    *reinterpret_cast<uint2*>(oh + row*1024 + tid*4) =
        make_uint2(pack_h(v.x,v.y), pack_h(v.z,v.w));
}

// fp32 -> fp16 hi/lo elementwise split
__global__ __launch_bounds__(256) void splitk(const float4* __restrict__ in,
                                              half* __restrict__ oh, half* __restrict__ ol, long n4){
    long i = (long)blockIdx.x*256 + threadIdx.x;
    if (i >= n4) return;
    float4 v = in[i];
    float h0,l0,h1,l1,h2,l2,h3,l3;
    split2(v.x,h0,l0); split2(v.y,h1,l1); split2(v.z,h2,l2); split2(v.w,h3,l3);
    *reinterpret_cast<uint2*>(oh + i*4) = make_uint2(pack_h(h0,h1), pack_h(h2,h3));
    *reinterpret_cast<uint2*>(ol + i*4) = make_uint2(pack_h(l0,l1), pack_h(l2,l3));
}

// W [K,N] fp32 -> Wt [N,K] single fp16
__global__ __launch_bounds__(256) void wtsplit(const float* __restrict__ W,
                                               half* __restrict__ oh, int K, int N){
    __shared__ float tf[32][33];
    const int n0 = blockIdx.x*32, k0 = blockIdx.y*32;
    const int tx = threadIdx.x&31, ty = threadIdx.x>>5;
    #pragma unroll
    for(int i=0;i<4;i++) tf[ty+8*i][tx] = W[(long)(k0+ty+8*i)*N + n0+tx];
    __syncthreads();
    #pragma unroll
    for(int i=0;i<4;i++){
        long o = (long)(n0+ty+8*i)*K + k0+tx;
        oh[o] = __float2half_rn(tf[tx][ty+8*i]);
    }
}

// v [B,T,H*64] -> vt [B*H, 64, 1024] single fp16
__global__ __launch_bounds__(256) void vtrans(const half* __restrict__ ih, half* __restrict__ oh){
    __shared__ half th[32][34];
    const int t0 = blockIdx.x*32, d0 = blockIdx.y*32, bz = blockIdx.z;
    const int bb = bz/H_, hh = bz - bb*H_;
    const int tx = threadIdx.x&31, ty = threadIdx.x>>5;
    const long ib = ((long)bb*1024 + t0)*768 + hh*64 + d0;
    #pragma unroll
    for(int i=0;i<4;i++) th[ty+8*i][tx] = ih[ib + (long)(ty+8*i)*768 + tx];
    __syncthreads();
    const long ob = ((long)bz*64 + d0)*1024 + t0;
    #pragma unroll
    for(int i=0;i<4;i++) oh[ob + (long)(ty+8*i)*1024 + tx] = th[tx][ty+8*i];
}

extern "C" void kernel_launch(void* const* d_in, const int* in_sizes, int n_in,
                              void* d_out, int out_size)
{
    const float* x     = (const float*)d_in[0];
    const float* mask  = (const float*)d_in[1];
    const float* bias  = (const float*)d_in[2];
    const float* Wqkv  = (const float*)d_in[3];
    const float* bqkv  = (const float*)d_in[4];
    const float* Wproj = (const float*)d_in[5];
    const float* bproj = (const float*)d_in[6];
    float* out = (float*)d_out;

    half *xh,*xl,*wq,*wp,*qh,*ql,*kk,*vv,*vt,*ah,*yy;
    float *logits;
    cudaGetSymbolAddress((void**)&xh,g_xh);   cudaGetSymbolAddress((void**)&xl,g_xl);
    cudaGetSymbolAddress((void**)&wq,g_wq);   cudaGetSymbolAddress((void**)&wp,g_wp);
    cudaGetSymbolAddress((void**)&qh,g_qh);   cudaGetSymbolAddress((void**)&ql,g_ql);
    cudaGetSymbolAddress((void**)&kk,g_kk);   cudaGetSymbolAddress((void**)&vv,g_vv);
    cudaGetSymbolAddress((void**)&vt,g_vt);
    cudaGetSymbolAddress((void**)&ah,g_ah);   cudaGetSymbolAddress((void**)&yy,g_yy);
    cudaGetSymbolAddress((void**)&logits,g_logits);

    float* attn = ((long)out_size >= YN + AN) ? (out + YN) : logits;

    const int smemBig   = 92160;   // MODE 0/1: 3*(2*10240 + 10240)
    const int smemProj  = 61440;   // MODE 2:   3*(10240 + 10240)
    const int smemAV    = 46080;   // MODE 3:   3*(10240 + 5120)
    cudaFuncSetAttribute(gemm_tc<0>, cudaFuncAttributeMaxDynamicSharedMemorySize, smemBig);
    cudaFuncSetAttribute(gemm_tc<1>, cudaFuncAttributeMaxDynamicSharedMemorySize, smemBig);
    cudaFuncSetAttribute(gemm_tc<2>, cudaFuncAttributeMaxDynamicSharedMemorySize, smemProj);
    cudaFuncSetAttribute(gemm_tc<3>, cudaFuncAttributeMaxDynamicSharedMemorySize, smemAV);

    // 1) split x into fp16 hi/lo
    splitk<<<(YN/4+255)/256, 256>>>((const float4*)x, xh, xl, YN/4);
    // 2) transpose weights to [N,K] single fp16
    wtsplit<<<dim3(2304/32, 768/32), 256>>>(Wqkv, wq, 768, 2304);
    wtsplit<<<dim3(768/32, 768/32),  256>>>(Wproj, wp, 768, 768);
    // 3) qkv GEMM -> q(scaled, split) / k / v
    gemm_tc<0><<<dim3(18,32,1), 256, smemBig>>>(xh, xl, wq, bqkv, nullptr, nullptr, nullptr,
                                                qh, ql, kk, vv);
    // 4) transpose v -> [B*H,64,1024]
    vtrans<<<dim3(32,2,48), 256>>>(vv, vt);
    // 5) logits fp32 = q k^T + bias + mask
    gemm_tc<1><<<dim3(8,8,48), 256, smemBig>>>(qh, ql, kk, nullptr, bias, mask, logits,
                                               nullptr, nullptr, nullptr, nullptr);
    // 6) softmax -> attn fp32 + attn fp16
    softmax_kernel<<<48*1024, 256>>>(logits, attn, ah);
    // 7) y = attn @ v^T (single-product, single fp16 output)
    gemm_tc<3><<<dim3(1,8,48), 256, smemAV>>>(ah, nullptr, vt, nullptr, nullptr, nullptr, nullptr,
                                              yy, nullptr, nullptr, nullptr);
    // 8) out = y @ Wproj + bproj (single-product)
    gemm_tc<2><<<dim3(6,32,1), 256, smemProj>>>(yy, nullptr, wp, bproj, nullptr, nullptr, out,
                                                nullptr, nullptr, nullptr, nullptr);
}

// round 16
// speedup vs baseline: 1.5459x; 1.0162x over previous
#include <cuda_runtime.h>
#include <cuda_fp16.h>
#include <cstdint>

static constexpr int B_=4, T_=1024, C_=768, H_=12;
static constexpr long BT=4096, YN=BT*C_, AN=48L*1024*1024;

__device__ __align__(1024) half g_xh[YN], g_xl[YN];
__device__ __align__(1024) half g_wq[2304L*768];
__device__ __align__(1024) half g_wp[768L*768];
__device__ __align__(1024) half g_qh[YN], g_ql[YN];
__device__ __align__(1024) half g_kk[YN];
__device__ __align__(1024) half g_vv[YN], g_vt[YN];
__device__ __align__(1024) float g_logits[AN];
__device__ __align__(1024) half g_ah[AN];             // normalized attn (fp16)
__device__ __align__(1024) half g_yy[YN];             // y (fp16, single)

// ---------------- helpers ----------------
__device__ __forceinline__ uint32_t smem_u32(const void* p){
    uint32_t a; asm("{ .reg .u64 t; cvta.to.shared.u64 t, %1; cvt.u32.u64 %0, t; }":"=r"(a):"l"(p)); return a;
}
__device__ __forceinline__ void mma16816(float* c, const uint32_t* a, const uint32_t* b){
    asm volatile("mma.sync.aligned.m16n8k16.row.col.f32.f16.f16.f32 "
        "{%0,%1,%2,%3}, {%4,%5,%6,%7}, {%8,%9}, {%0,%1,%2,%3};"
        : "+f"(c[0]),"+f"(c[1]),"+f"(c[2]),"+f"(c[3])
        : "r"(a[0]),"r"(a[1]),"r"(a[2]),"r"(a[3]),"r"(b[0]),"r"(b[1]));
}
__device__ __forceinline__ void ldsm4(uint32_t* r, uint32_t addr){
    asm volatile("ldmatrix.sync.aligned.m8n8.x4.shared.b16 {%0,%1,%2,%3}, [%4];"
        : "=r"(r[0]),"=r"(r[1]),"=r"(r[2]),"=r"(r[3]) : "r"(addr));
}
__device__ __forceinline__ void cpasync16(uint32_t dst, const void* src){
    asm volatile("cp.async.cg.shared.global [%0], [%1], 16;" :: "r"(dst), "l"(src));
}
__device__ __forceinline__ void cpcommit(){ asm volatile("cp.async.commit_group;" ::: "memory"); }
template<int N> __device__ __forceinline__ void cpwait(){ asm volatile("cp.async.wait_group %0;" :: "n"(N) : "memory"); }
__device__ __forceinline__ uint32_t pack_h(float a, float b){
    half2 t = __floats2half2_rn(a,b);
    return *reinterpret_cast<uint32_t*>(&t);
}
__device__ __forceinline__ void split2(float v, float& h, float& l){
    half hb = __float2half_rn(v); h = __half2float(hb); l = v - h;
}

// ---------------------------------------------------------------------------
// TN-form fp16 tensor-core GEMM. A split hi/lo (2 products) for MODE 0/1;
// single-product A for MODE 2 (proj) and MODE 3 (AV). 3-stage cp.async
// pipeline with ONE sync per K-tile; B fragments for both kf per ldsm4.
// A:[M,K], B:[N,K]; C = A*B^T fp32.
// MODE 0:qkv  1:logits(fp32)  2:proj  3:AV
// ---------------------------------------------------------------------------
template<int MODE>
__global__ __launch_bounds__(256)
void gemm_tc(const half* __restrict__ Ah, const half* __restrict__ Al,
             const half* __restrict__ Bs,
             const float* __restrict__ bias1, const float* __restrict__ biasM,
             const float* __restrict__ maskM, float* __restrict__ outF,
             half* __restrict__ o1h, half* __restrict__ o1l,
             half* __restrict__ o2h, half* __restrict__ o3h)
{
    constexpr int TN  = (MODE==3)?64:128;
    constexpr int NF  = TN/32;
    constexpr int NPROD = (MODE>=2)?1:2;       // A-side products
    constexpr int KT  = (MODE==1)?64:((MODE==3)?1024:768);
    constexpr long LDA = (MODE==3)?1024:768;
    constexpr long LDB = (MODE==3)?1024:768;
    constexpr int NKT = KT/32;
    constexpr uint32_t TSA  = 10240u;          // 128x32 fp16 tile, 80B pitch
    constexpr uint32_t TSB  = TN*80u;
    constexpr uint32_t BUFB = (uint32_t)NPROD*TSA + TSB;

    extern __shared__ half smem[];
    const uint32_t sb0 = smem_u32(smem);

    const int tid = threadIdx.x, wid = tid>>5, lane = tid&31;
    const int wr = wid>>2, wc = wid&3;
    const int m_w = wr*64, n_w = wc*(TN/4);
    const int m0 = blockIdx.y*128, n0 = blockIdx.x*TN;
    const int bz = blockIdx.z, bb = bz/H_, hh = bz - bb*H_;

    long aOff, bOff;
    if (MODE==1){ aOff = ((long)bb*1024 + m0)*768 + hh*64; bOff = ((long)bb*1024 + n0)*768 + hh*64; }
    else if (MODE==3){ aOff = (long)bz*1048576 + (long)m0*1024; bOff = (long)bz*65536; }
    else { aOff = (long)m0*LDA; bOff = (long)n0*LDB; }
    const half *pAh=Ah+aOff, *pAl=(NPROD==2)?(Al+aOff):nullptr, *pB=Bs+bOff;

    float acc[4][NF][4];
    #pragma unroll
    for(int i=0;i<4;i++)
        #pragma unroll
        for(int j=0;j<NF;j++)
            #pragma unroll
            for(int k=0;k<4;k++) acc[i][j][k]=0.f;

    const uint32_t aAddrB = sb0 + (uint32_t)(m_w + (lane&15))*80u + (uint32_t)(lane>>4)*16u;
    // B: 4 lane-groups cover k-bytes 0..64 => one ldsm4 gives both kf halves
    const uint32_t bAddrB = sb0 + (uint32_t)(n_w + (lane&7))*80u + (uint32_t)((lane>>3)&3)*16u;

    auto issue = [&](int kt, int buf){
        const long k0 = (long)kt*32;
        const uint32_t base = sb0 + (uint32_t)buf*BUFB;
        #pragma unroll
        for(int it=0; it<2*NPROD; ++it){           // A tiles: 512 chunks per product
            const int i = tid + it*256;
            const int t = i>>9, j = i&511, r = j>>2, c = j&3;
            const half* src = (t? pAl : pAh) + (long)r*LDA + k0 + c*8;
            cpasync16(base + (uint32_t)t*TSA + (uint32_t)(r*80 + c*16), src);
        }
        #pragma unroll
        for(int it=0; it<TN/64; ++it){             // B single: TN*4 x 16B
            const int i = tid + it*256;
            const int r = i>>2, c = i&3;
            const half* src = pB + (long)r*LDB + k0 + c*8;
            cpasync16(base + (uint32_t)NPROD*TSA + (uint32_t)(r*80 + c*16), src);
        }
        cpcommit();
    };

    // 3-stage prologue
    issue(0, 0);
    if (NKT > 1) issue(1, 1);

    int cb = 0;
    for(int kt=0; kt<NKT; ++kt){
        if (kt+1 < NKT) cpwait<1>(); else cpwait<0>();
        __syncthreads();

        const uint32_t aH = aAddrB + (uint32_t)cb*BUFB;
        const uint32_t bB = bAddrB + (uint32_t)cb*BUFB + (uint32_t)NPROD*TSA;

        uint32_t b4[NF][4];
        #pragma unroll
        for(int nf=0; nf<NF; ++nf) ldsm4(b4[nf], bB + (uint32_t)nf*640u);

        #pragma unroll
        for(int kf=0; kf<2; ++kf){
            uint32_t a4[4][4];
            #pragma unroll
            for(int mf=0; mf<4; ++mf) ldsm4(a4[mf], aH + (uint32_t)mf*1280u + (uint32_t)kf*32u);
            #pragma unroll
            for(int mf=0; mf<4; ++mf)
                #pragma unroll
                for(int nf=0; nf<NF; ++nf) mma16816(acc[mf][nf], a4[mf], &b4[nf][2*kf]);   // Ah*B
            if (NPROD==2){
                #pragma unroll
                for(int mf=0; mf<4; ++mf) ldsm4(a4[mf], aH + TSA + (uint32_t)mf*1280u + (uint32_t)kf*32u);
                #pragma unroll
                for(int mf=0; mf<4; ++mf)
                    #pragma unroll
                    for(int nf=0; nf<NF; ++nf) mma16816(acc[mf][nf], a4[mf], &b4[nf][2*kf]);   // Al*B
            }
        }
        // issue next tile AFTER compute: writes buf (kt+2)%3 == (kt-1)%3, which
        // every warp finished reading before this iteration's barrier.
        if (kt+2 < NKT) issue(kt+2, (kt+2)%3);
        cb = (cb+1)%3;
    }

    // ---------------- direct fragment epilogue ----------------
    const int qd = lane>>2, rr = lane&3;
    #pragma unroll
    for(int mf=0;mf<4;++mf){
        #pragma unroll
        for(int nf=0;nf<NF;++nf){
            const float* c = acc[mf][nf];
            const int mrow0 = m_w + mf*16 + qd;
            const int ncol  = n_w + nf*8 + rr*2;
            #pragma unroll
            for(int h2=0;h2<2;++h2){
                const int mloc = mrow0 + h2*8;
                float v0 = c[h2*2+0], v1 = c[h2*2+1];
                if (MODE==1){
                    const long rowg  = (long)bz*1048576 + (long)(m0+mloc)*1024 + n0 + ncol;
                    const long maskg = (long)bb*1048576 + (long)(m0+mloc)*1024 + n0 + ncol;
                    float2 bm = *reinterpret_cast<const float2*>(biasM + rowg);
                    float2 mk = *reinterpret_cast<const float2*>(maskM + maskg);
                    float2 o; o.x = v0 + bm.x + mk.x; o.y = v1 + bm.y + mk.y;
                    *reinterpret_cast<float2*>(outF + rowg) = o;
                } else if (MODE==2){
                    const int ng = n0 + ncol;
                    float2 o; o.x = v0 + bias1[ng]; o.y = v1 + bias1[ng+1];
                    *reinterpret_cast<float2*>(outF + (long)(m0+mloc)*768 + ng) = o;
                } else if (MODE==0){
                    const int ng = n0 + ncol;
                    v0 += bias1[ng]; v1 += bias1[ng+1];
                    if (n0 < 768){            // q: scaled, split hi/lo
                        v0 *= 0.125f; v1 *= 0.125f;
                        float h0,l0,h1,l1; split2(v0,h0,l0); split2(v1,h1,l1);
                        const long ob = (long)(m0+mloc)*768 + ng;
                        *reinterpret_cast<uint32_t*>(o1h+ob) = pack_h(h0,h1);
                        *reinterpret_cast<uint32_t*>(o1l+ob) = pack_h(l0,l1);
                    } else if (n0 < 1536){    // k: single fp16
                        const long ob = (long)(m0+mloc)*768 + ng - 768;
                        *reinterpret_cast<uint32_t*>(o2h+ob) = pack_h(v0,v1);
                    } else {                  // v: single fp16
                        const long ob = (long)(m0+mloc)*768 + ng - 1536;
                        *reinterpret_cast<uint32_t*>(o3h+ob) = pack_h(v0,v1);
                    }
                } else { // MODE 3: y single fp16
                    const long ob = ((long)bb*1024 + m0 + mloc)*768 + hh*64 + ncol;
                    *reinterpret_cast<uint32_t*>(o1h+ob) = pack_h(v0,v1);
                }
            }
        }
    }
}

// Warp-per-row softmax: 8 rows per 256-thread block; lane j holds float4s at
// indices lane + 32*j (coalesced). No barriers, no smem — pure shfl reductions.
__global__ __launch_bounds__(256) void softmax_kernel(const float* __restrict__ in, float* __restrict__ out,
                                                      half* __restrict__ oh){
    const int lane = threadIdx.x & 31;
    const long row = (long)blockIdx.x*8 + (threadIdx.x >> 5);
    const float4* ip = reinterpret_cast<const float4*>(in + row*1024);
    float4 v[8];
    #pragma unroll
    for(int j=0;j<8;j++) v[j] = ip[lane + 32*j];

    float m = -1e30f;
    #pragma unroll
    for(int j=0;j<8;j++) m = fmaxf(m, fmaxf(fmaxf(v[j].x,v[j].y), fmaxf(v[j].z,v[j].w)));
    #pragma unroll
    for(int o=16;o;o>>=1) m = fmaxf(m, __shfl_xor_sync(0xffffffffu,m,o));

    float s = 0.f;
    #pragma unroll
    for(int j=0;j<8;j++){
        v[j].x=__expf(v[j].x-m); v[j].y=__expf(v[j].y-m);
        v[j].z=__expf(v[j].z-m); v[j].w=__expf(v[j].w-m);
        s += v[j].x+v[j].y+v[j].z+v[j].w;
    }
    #pragma unroll
    for(int o=16;o;o>>=1) s += __shfl_xor_sync(0xffffffffu,s,o);
    const float inv = 1.0f/s;

    float4* op = reinterpret_cast<float4*>(out + row*1024);
    uint2*  hp = reinterpret_cast<uint2*>(oh + row*1024);
    #pragma unroll
    for(int j=0;j<8;j++){
        v[j].x*=inv; v[j].y*=inv; v[j].z*=inv; v[j].w*=inv;
        op[lane + 32*j] = v[j];
        hp[lane + 32*j] = make_uint2(pack_h(v[j].x,v[j].y), pack_h(v[j].z,v[j].w));
    }
}

// fp32 -> fp16 hi/lo elementwise split
__global__ __launch_bounds__(256) void splitk(const float4* __restrict__ in,
                                              half* __restrict__ oh, half* __restrict__ ol, long n4){
    long i = (long)blockIdx.x*256 + threadIdx.x;
    if (i >= n4) return;
    float4 v = in[i];
    float h0,l0,h1,l1,h2,l2,h3,l3;
    split2(v.x,h0,l0); split2(v.y,h1,l1); split2(v.z,h2,l2); split2(v.w,h3,l3);
    *reinterpret_cast<uint2*>(oh + i*4) = make_uint2(pack_h(h0,h1), pack_h(h2,h3));
    *reinterpret_cast<uint2*>(ol + i*4) = make_uint2(pack_h(l0,l1), pack_h(l2,l3));
}

// W [K,N] fp32 -> Wt [N,K] single fp16
__global__ __launch_bounds__(256) void wtsplit(const float* __restrict__ W,
                                               half* __restrict__ oh, int K, int N){
    __shared__ float tf[32][33];
    const int n0 = blockIdx.x*32, k0 = blockIdx.y*32;
    const int tx = threadIdx.x&31, ty = threadIdx.x>>5;
    #pragma unroll
    for(int i=0;i<4;i++) tf[ty+8*i][tx] = W[(long)(k0+ty+8*i)*N + n0+tx];
    __syncthreads();
    #pragma unroll
    for(int i=0;i<4;i++){
        long o = (long)(n0+ty+8*i)*K + k0+tx;
        oh[o] = __float2half_rn(tf[tx][ty+8*i]);
    }
}

// v [B,T,H*64] -> vt [B*H, 64, 1024] single fp16
__global__ __launch_bounds__(256) void vtrans(const half* __restrict__ ih, half* __restrict__ oh){
    __shared__ half th[32][34];
    const int t0 = blockIdx.x*32, d0 = blockIdx.y*32, bz = blockIdx.z;
    const int bb = bz/H_, hh = bz - bb*H_;
    const int tx = threadIdx.x&31, ty = threadIdx.x>>5;
    const long ib = ((long)bb*1024 + t0)*768 + hh*64 + d0;
    #pragma unroll
    for(int i=0;i<4;i++) th[ty+8*i][tx] = ih[ib + (long)(ty+8*i)*768 + tx];
    __syncthreads();
    const long ob = ((long)bz*64 + d0)*1024 + t0;
    #pragma unroll
    for(int i=0;i<4;i++) oh[ob + (long)(ty+8*i)*1024 + tx] = th[tx][ty+8*i];
}

extern "C" void kernel_launch(void* const* d_in, const int* in_sizes, int n_in,
                              void* d_out, int out_size)
{
    const float* x     = (const float*)d_in[0];
    const float* mask  = (const float*)d_in[1];
    const float* bias  = (const float*)d_in[2];
    const float* Wqkv  = (const float*)d_in[3];
    const float* bqkv  = (const float*)d_in[4];
    const float* Wproj = (const float*)d_in[5];
    const float* bproj = (const float*)d_in[6];
    float* out = (float*)d_out;

    half *xh,*xl,*wq,*wp,*qh,*ql,*kk,*vv,*vt,*ah,*yy;
    float *logits;
    cudaGetSymbolAddress((void**)&xh,g_xh);   cudaGetSymbolAddress((void**)&xl,g_xl);
    cudaGetSymbolAddress((void**)&wq,g_wq);   cudaGetSymbolAddress((void**)&wp,g_wp);
    cudaGetSymbolAddress((void**)&qh,g_qh);   cudaGetSymbolAddress((void**)&ql,g_ql);
    cudaGetSymbolAddress((void**)&kk,g_kk);   cudaGetSymbolAddress((void**)&vv,g_vv);
    cudaGetSymbolAddress((void**)&vt,g_vt);
    cudaGetSymbolAddress((void**)&ah,g_ah);   cudaGetSymbolAddress((void**)&yy,g_yy);
    cudaGetSymbolAddress((void**)&logits,g_logits);

    float* attn = ((long)out_size >= YN + AN) ? (out + YN) : logits;

    const int smemBig   = 92160;   // MODE 0/1: 3*(2*10240 + 10240)
    const int smemProj  = 61440;   // MODE 2:   3*(10240 + 10240)
    const int smemAV    = 46080;   // MODE 3:   3*(10240 + 5120)
    cudaFuncSetAttribute(gemm_tc<0>, cudaFuncAttributeMaxDynamicSharedMemorySize, smemBig);
    cudaFuncSetAttribute(gemm_tc<1>, cudaFuncAttributeMaxDynamicSharedMemorySize, smemBig);
    cudaFuncSetAttribute(gemm_tc<2>, cudaFuncAttributeMaxDynamicSharedMemorySize, smemProj);
    cudaFuncSetAttribute(gemm_tc<3>, cudaFuncAttributeMaxDynamicSharedMemorySize, smemAV);

    // 1) split x into fp16 hi/lo
    splitk<<<(YN/4+255)/256, 256>>>((const float4*)x, xh, xl, YN/4);
    // 2) transpose weights to [N,K] single fp16
    wtsplit<<<dim3(2304/32, 768/32), 256>>>(Wqkv, wq, 768, 2304);
    wtsplit<<<dim3(768/32, 768/32),  256>>>(Wproj, wp, 768, 768);
    // 3) qkv GEMM -> q(scaled, split) / k / v
    gemm_tc<0><<<dim3(18,32,1), 256, smemBig>>>(xh, xl, wq, bqkv, nullptr, nullptr, nullptr,
                                                qh, ql, kk, vv);
    // 4) transpose v -> [B*H,64,1024]
    vtrans<<<dim3(32,2,48), 256>>>(vv, vt);
    // 5) logits fp32 = q k^T + bias + mask
    gemm_tc<1><<<dim3(8,8,48), 256, smemBig>>>(qh, ql, kk, nullptr, bias, mask, logits,
                                               nullptr, nullptr, nullptr, nullptr);
    // 6) softmax (warp-per-row) -> attn fp32 + attn fp16
    softmax_kernel<<<48*1024/8, 256>>>(logits, attn, ah);
    // 7) y = attn @ v^T (single-product, single fp16 output)
    gemm_tc<3><<<dim3(1,8,48), 256, smemAV>>>(ah, nullptr, vt, nullptr, nullptr, nullptr, nullptr,
                                              yy, nullptr, nullptr, nullptr);
    // 8) out = y @ Wproj + bproj (single-product)
    gemm_tc<2><<<dim3(6,32,1), 256, smemProj>>>(yy, nullptr, wp, bproj, nullptr, nullptr, out,
                                                nullptr, nullptr, nullptr, nullptr);
}